// round 3
// baseline (speedup 1.0000x reference)
#include <cuda_runtime.h>
#include <math.h>

// Problem constants (fixed by the reference)
#define NODES 50000
#define EDGES 800000
#define FIN   128
#define FH    256
#define FOUT  10
#define NGRAPH 128

// ---------------- scratch (device globals; no runtime allocation) ----------
__device__ float g_bufA[(size_t)NODES * FH];   // 51.2 MB
__device__ float g_bufB[(size_t)NODES * FH];   // 51.2 MB
__device__ float g_dinv[NODES];
__device__ int   g_deg[NODES];
__device__ int   g_rowptr[NODES + 1];
__device__ int   g_cursor[NODES];
__device__ int   g_src[EDGES];
__device__ float g_norm[EDGES];
__device__ float g_pooled[NGRAPH * FH];
__device__ int   g_gcount[NGRAPH];
__device__ int   g_gstart[NGRAPH + 1];
__device__ int   g_is64;     // 1 if index inputs are int64, 0 if int32

// ---------------- dtype probe ----------------------------------------------
// If edge_index is int64 (values < 2^31, nonneg), viewing it as int32 gives
// [lo,hi,lo,hi,...] with every odd word == 0. If it is int32, odd words are
// ordinary node indices (all-zero across 256 spread samples ~ impossible).
__global__ void k_detect(const int* __restrict__ ei32) {
    __shared__ int nonzero;
    if (threadIdx.x == 0) nonzero = 0;
    __syncthreads();
    // sample odd positions spread across the full 2*EDGES int32 words
    int stride = (2 * EDGES) / 256;            // 6250
    int pos = threadIdx.x * stride + 1;        // odd offsets (stride even)
    if (ei32[pos | 1] != 0) atomicOr(&nonzero, 1);
    __syncthreads();
    if (threadIdx.x == 0) g_is64 = nonzero ? 0 : 1;
}

__device__ __forceinline__ int load_idx(const void* p, size_t i) {
    return g_is64 ? (int)((const long long*)p)[i] : ((const int*)p)[i];
}

// ---------------- setup kernels --------------------------------------------
__global__ void k_zero() {
    int i = blockIdx.x * blockDim.x + threadIdx.x;
    if (i < NODES) { g_deg[i] = 0; g_cursor[i] = 0; }
    if (i < NGRAPH) g_gcount[i] = 0;
}

__global__ void k_deg(const void* __restrict__ ei) {
    int e = blockIdx.x * blockDim.x + threadIdx.x;
    if (e >= EDGES) return;
    int col = load_idx(ei, (size_t)EDGES + e);
    atomicAdd(&g_deg[col], 1);
}

__global__ void k_dinv() {
    int i = blockIdx.x * blockDim.x + threadIdx.x;
    if (i < NODES) g_dinv[i] = rsqrtf((float)g_deg[i] + 1.0f);
}

// exclusive scan of g_deg -> g_rowptr, single block of 1024 threads
__global__ void k_scan_rowptr() {
    __shared__ int sm[1024];
    __shared__ int carry;
    int t = threadIdx.x;
    if (t == 0) carry = 0;
    __syncthreads();
    for (int base = 0; base < NODES; base += 1024) {
        int i = base + t;
        int v = (i < NODES) ? g_deg[i] : 0;
        sm[t] = v;
        __syncthreads();
        for (int off = 1; off < 1024; off <<= 1) {
            int add = (t >= off) ? sm[t - off] : 0;
            __syncthreads();
            sm[t] += add;
            __syncthreads();
        }
        if (i < NODES) g_rowptr[i] = carry + sm[t] - v;   // exclusive
        __syncthreads();
        if (t == 0) carry += sm[1023];
        __syncthreads();
    }
    if (t == 0) g_rowptr[NODES] = carry;
}

__global__ void k_scatter(const void* __restrict__ ei) {
    int e = blockIdx.x * blockDim.x + threadIdx.x;
    if (e >= EDGES) return;
    int row = load_idx(ei, e);
    int col = load_idx(ei, (size_t)EDGES + e);
    int pos = atomicAdd(&g_cursor[col], 1);
    int slot = g_rowptr[col] + pos;
    g_src[slot]  = row;
    g_norm[slot] = g_dinv[row] * g_dinv[col];
}

// ---------------- aggregation: agg[i] = dinv[i]^2*h[i] + sum norm*h[src] ----
// Layer 0: input = external x [N,128], output = g_bufB
__global__ void k_agg_x(const float* __restrict__ h) {
    int node = blockIdx.x;
    int t = threadIdx.x;                 // 128
    int s = g_rowptr[node], e = g_rowptr[node + 1];
    float di = g_dinv[node];
    float acc0 = di * di * h[(size_t)node * FIN + t];
    float acc1 = 0.f;
    int j = s;
    for (; j + 1 < e; j += 2) {
        int s0 = g_src[j], s1 = g_src[j + 1];
        float n0 = g_norm[j], n1 = g_norm[j + 1];
        acc0 += n0 * h[(size_t)s0 * FIN + t];
        acc1 += n1 * h[(size_t)s1 * FIN + t];
    }
    if (j < e) acc0 += g_norm[j] * h[(size_t)g_src[j] * FIN + t];
    g_bufB[(size_t)node * FIN + t] = acc0 + acc1;
}

// Layers 1,2: input = g_bufA [N,256], output = g_bufB
__global__ void k_agg_h() {
    int node = blockIdx.x;
    int t = threadIdx.x;                 // 256
    int s = g_rowptr[node], e = g_rowptr[node + 1];
    float di = g_dinv[node];
    float acc0 = di * di * g_bufA[(size_t)node * FH + t];
    float acc1 = 0.f;
    int j = s;
    for (; j + 1 < e; j += 2) {
        int s0 = g_src[j], s1 = g_src[j + 1];
        float n0 = g_norm[j], n1 = g_norm[j + 1];
        acc0 += n0 * g_bufA[(size_t)s0 * FH + t];
        acc1 += n1 * g_bufA[(size_t)s1 * FH + t];
    }
    if (j < e) acc0 += g_norm[j] * g_bufA[(size_t)g_src[j] * FH + t];
    g_bufB[(size_t)node * FH + t] = acc0 + acc1;
}

// ---------------- tiled SGEMM + relu: g_bufA = relu(g_bufB[M,K] @ W[K,256]) -
#define BM 64
#define BN 64
#define BK 16
__global__ void k_gemm_relu(const float* __restrict__ B, int K) {
    __shared__ float As[BK][BM + 1];
    __shared__ float Bs[BK][BN];
    int bm = blockIdx.y * BM, bn = blockIdx.x * BN;
    int tid = threadIdx.x;              // 256
    int tx = tid & 15, ty = tid >> 4;   // 16x16
    float acc[4][4] = {};
    for (int k0 = 0; k0 < K; k0 += BK) {
        #pragma unroll
        for (int i = 0; i < 4; i++) {
            int idx = tid + i * 256;        // 0..1023 over 64x16 A tile
            int r = idx >> 4, c = idx & 15;
            int gr = bm + r;
            As[c][r] = (gr < NODES) ? g_bufB[(size_t)gr * K + k0 + c] : 0.f;
        }
        #pragma unroll
        for (int i = 0; i < 4; i++) {
            int idx = tid + i * 256;        // 0..1023 over 16x64 B tile
            int r = idx >> 6, c = idx & 63;
            Bs[r][c] = B[(size_t)(k0 + r) * FH + bn + c];
        }
        __syncthreads();
        #pragma unroll
        for (int k = 0; k < BK; k++) {
            float a[4], b[4];
            #pragma unroll
            for (int i = 0; i < 4; i++) a[i] = As[k][ty * 4 + i];
            #pragma unroll
            for (int i = 0; i < 4; i++) b[i] = Bs[k][tx * 4 + i];
            #pragma unroll
            for (int i = 0; i < 4; i++)
                #pragma unroll
                for (int j = 0; j < 4; j++) acc[i][j] += a[i] * b[j];
        }
        __syncthreads();
    }
    #pragma unroll
    for (int i = 0; i < 4; i++) {
        int gr = bm + ty * 4 + i;
        if (gr < NODES) {
            #pragma unroll
            for (int j = 0; j < 4; j++) {
                float v = acc[i][j];
                v = v > 0.f ? v : 0.f;
                g_bufA[(size_t)gr * FH + bn + tx * 4 + j] = v;
            }
        }
    }
}

// ---------------- pooling ---------------------------------------------------
__global__ void k_gcount(const void* __restrict__ batch) {
    int i = blockIdx.x * blockDim.x + threadIdx.x;
    if (i < NODES) atomicAdd(&g_gcount[load_idx(batch, i)], 1);
}

__global__ void k_scan_graphs() {   // 128 threads, 1 block
    __shared__ int sm[NGRAPH];
    int t = threadIdx.x;
    int v = g_gcount[t];
    sm[t] = v;
    __syncthreads();
    for (int off = 1; off < NGRAPH; off <<= 1) {
        int add = (t >= off) ? sm[t - off] : 0;
        __syncthreads();
        sm[t] += add;
        __syncthreads();
    }
    g_gstart[t] = sm[t] - v;    // exclusive
    if (t == NGRAPH - 1) g_gstart[NGRAPH] = sm[t];
}

__global__ void k_pool() {   // grid = G, block = 256; reads g_bufA
    int g = blockIdx.x, t = threadIdx.x;
    int s = g_gstart[g], e = g_gstart[g + 1];
    float sum = 0.f;
    for (int i = s; i < e; i++) sum += g_bufA[(size_t)i * FH + t];
    int cnt = e - s;
    g_pooled[g * FH + t] = sum / (float)(cnt > 0 ? cnt : 1);
}

// ---------------- MLP head + log_softmax + sigmoid --------------------------
__global__ void k_head(const float* __restrict__ Wm1, const float* __restrict__ bm1,
                       const float* __restrict__ Wm2, const float* __restrict__ bm2,
                       float* __restrict__ out) {     // grid = G, block = 256
    __shared__ float sp[FH];
    __shared__ float sh[FH];
    __shared__ float sl[FOUT];
    __shared__ float s_m, s_lse;
    int g = blockIdx.x, t = threadIdx.x;
    sp[t] = g_pooled[g * FH + t];
    __syncthreads();
    float acc = bm1[t];
    #pragma unroll 8
    for (int k = 0; k < FH; k++) acc += sp[k] * Wm1[k * FH + t];
    sh[t] = acc > 0.f ? acc : 0.f;
    __syncthreads();
    if (t < FOUT) {
        float a = bm2[t];
        for (int k = 0; k < FH; k++) a += sh[k] * Wm2[k * FOUT + t];
        sl[t] = a;
    }
    __syncthreads();
    if (t == 0) {
        float m = sl[0];
        for (int o = 1; o < FOUT; o++) m = fmaxf(m, sl[o]);
        float s = 0.f;
        for (int o = 0; o < FOUT; o++) s += expf(sl[o] - m);
        s_m = m; s_lse = logf(s);
    }
    __syncthreads();
    if (t < FOUT) {
        float v = sl[t];
        out[g * FOUT + t]                       = v - s_m - s_lse;          // log_softmax
        out[NGRAPH * FOUT + g * FOUT + t]       = 1.0f / (1.0f + expf(-v)); // sigmoid
        out[2 * NGRAPH * FOUT + g * FOUT + t]   = v;                         // logits
    }
}

// ---------------- launch ----------------------------------------------------
extern "C" void kernel_launch(void* const* d_in, const int* in_sizes, int n_in,
                              void* d_out, int out_size) {
    const float* x     = (const float*)d_in[0];
    const void*  ei    = d_in[1];               // int32 or int64, detected on device
    // d_in[2] = edge_weight (ignored by the reference)
    const void*  batch = d_in[3];
    const float* W0  = (const float*)d_in[4];
    const float* W1  = (const float*)d_in[5];
    const float* W2  = (const float*)d_in[6];
    const float* Wm1 = (const float*)d_in[7];
    const float* bm1 = (const float*)d_in[8];
    const float* Wm2 = (const float*)d_in[9];
    const float* bm2 = (const float*)d_in[10];
    float* out = (float*)d_out;

    // ---- detect index dtype, then build graph structure
    k_detect<<<1, 256>>>((const int*)ei);
    k_zero<<<(NODES + 255) / 256, 256>>>();
    k_deg<<<(EDGES + 255) / 256, 256>>>(ei);
    k_dinv<<<(NODES + 255) / 256, 256>>>();
    k_scan_rowptr<<<1, 1024>>>();
    k_scatter<<<(EDGES + 255) / 256, 256>>>(ei);

    dim3 ggrid((FH + BN - 1) / BN, (NODES + BM - 1) / BM);   // (4, 782)

    // ---- layer 0: agg(x) [N,128] -> relu(@W0) [N,256]
    k_agg_x<<<NODES, FIN>>>(x);
    k_gemm_relu<<<ggrid, 256>>>(W0, FIN);
    // ---- layer 1
    k_agg_h<<<NODES, FH>>>();
    k_gemm_relu<<<ggrid, 256>>>(W1, FH);
    // ---- layer 2
    k_agg_h<<<NODES, FH>>>();
    k_gemm_relu<<<ggrid, 256>>>(W2, FH);

    // ---- mean pool per graph (batch is sorted)
    k_gcount<<<(NODES + 255) / 256, 256>>>(batch);
    k_scan_graphs<<<1, NGRAPH>>>();
    k_pool<<<NGRAPH, FH>>>();

    // ---- head
    k_head<<<NGRAPH, FH>>>(Wm1, bm1, Wm2, bm2, out);
}

// round 6
// speedup vs baseline: 1.2961x; 1.2961x over previous
#include <cuda_runtime.h>
#include <cuda_bf16.h>
#include <math.h>
#include <stdint.h>

// Problem constants (fixed by the reference)
#define NODES 50000
#define EDGES 800000
#define FIN   128
#define FH    256
#define FOUT  10
#define NGRAPH 128

__device__ __forceinline__ uint32_t smem_u32(const void* p) {
    uint32_t a;
    asm("{ .reg .u64 t; cvta.to.shared.u64 t, %1; cvt.u32.u64 %0, t; }" : "=r"(a) : "l"(p));
    return a;
}
__device__ __forceinline__ uint32_t sw128(uint32_t off) { return off ^ ((off >> 3) & 0x70); }

// ================= scratch (device globals; no runtime allocation) ==========
__device__ float          g_bufA[(size_t)NODES * FH];     // h (fp32)
__device__ __nv_bfloat16  g_Ahi[(size_t)NODES * FH];      // agg output, bf16 high
__device__ __nv_bfloat16  g_Alo[(size_t)NODES * FH];      // agg output, bf16 low
__device__ __nv_bfloat16  g_Whi[FH * FH];                 // weight, [N=256][K] bf16 high
__device__ __nv_bfloat16  g_Wlo[FH * FH];
__device__ float g_dinv[NODES];
__device__ int   g_deg[NODES];
__device__ int   g_rowptr[NODES + 1];
__device__ int   g_cursor[NODES];
__device__ int   g_src[EDGES];
__device__ float g_norm[EDGES];
__device__ float g_pooled[NGRAPH * FH];
__device__ int   g_gcount[NGRAPH];
__device__ int   g_gstart[NGRAPH + 1];
__device__ int   g_is64;

// ================= dtype probe =============================================
__global__ void k_detect(const int* __restrict__ ei32) {
    __shared__ int nonzero;
    if (threadIdx.x == 0) nonzero = 0;
    __syncthreads();
    int stride = (2 * EDGES) / 256;
    int pos = threadIdx.x * stride + 1;
    if (ei32[pos | 1] != 0) atomicOr(&nonzero, 1);
    __syncthreads();
    if (threadIdx.x == 0) g_is64 = nonzero ? 0 : 1;
}
__device__ __forceinline__ int load_idx(const void* p, size_t i) {
    return g_is64 ? (int)((const long long*)p)[i] : ((const int*)p)[i];
}

// ================= setup ====================================================
__global__ void k_zero() {
    int i = blockIdx.x * blockDim.x + threadIdx.x;
    if (i < NODES) { g_deg[i] = 0; g_cursor[i] = 0; }
    if (i < NGRAPH) g_gcount[i] = 0;
}
__global__ void k_deg(const void* __restrict__ ei) {
    int e = blockIdx.x * blockDim.x + threadIdx.x;
    if (e >= EDGES) return;
    atomicAdd(&g_deg[load_idx(ei, (size_t)EDGES + e)], 1);
}
__global__ void k_dinv() {
    int i = blockIdx.x * blockDim.x + threadIdx.x;
    if (i < NODES) g_dinv[i] = rsqrtf((float)g_deg[i] + 1.0f);
}
// shuffle-based exclusive scan of g_deg -> g_rowptr, single block 1024 threads
__global__ void k_scan_rowptr() {
    __shared__ int wsum[32];
    __shared__ int carry;
    int t = threadIdx.x, lane = t & 31, w = t >> 5;
    if (t == 0) carry = 0;
    __syncthreads();
    for (int base = 0; base < NODES; base += 1024) {
        int i = base + t;
        int v = (i < NODES) ? g_deg[i] : 0;
        int x = v;
        #pragma unroll
        for (int off = 1; off < 32; off <<= 1) {
            int y = __shfl_up_sync(0xFFFFFFFFu, x, off);
            if (lane >= off) x += y;
        }
        if (lane == 31) wsum[w] = x;
        __syncthreads();
        if (w == 0) {
            int s = wsum[lane];
            #pragma unroll
            for (int off = 1; off < 32; off <<= 1) {
                int y = __shfl_up_sync(0xFFFFFFFFu, s, off);
                if (lane >= off) s += y;
            }
            wsum[lane] = s;
        }
        __syncthreads();
        int woff = (w > 0) ? wsum[w - 1] : 0;
        if (i < NODES) g_rowptr[i] = carry + woff + x - v;
        __syncthreads();
        if (t == 0) carry += wsum[31];
        __syncthreads();
    }
    if (t == 0) g_rowptr[NODES] = carry;
}
__global__ void k_scatter(const void* __restrict__ ei) {
    int e = blockIdx.x * blockDim.x + threadIdx.x;
    if (e >= EDGES) return;
    int row = load_idx(ei, e);
    int col = load_idx(ei, (size_t)EDGES + e);
    int pos = atomicAdd(&g_cursor[col], 1);
    int slot = g_rowptr[col] + pos;
    g_src[slot]  = row;
    g_norm[slot] = g_dinv[row] * g_dinv[col];
}

// ================= aggregation (writes bf16 hi/lo staging) ==================
__device__ __forceinline__ void split_store(float v, size_t idx) {
    __nv_bfloat16 hi = __float2bfloat16(v);
    g_Ahi[idx] = hi;
    g_Alo[idx] = __float2bfloat16(v - __bfloat162float(hi));
}
__global__ void k_agg_x(const float* __restrict__ h) {
    int node = blockIdx.x, t = threadIdx.x;         // 128 threads
    int s = g_rowptr[node], e = g_rowptr[node + 1];
    float di = g_dinv[node];
    float a0 = di * di * h[(size_t)node * FIN + t], a1 = 0.f, a2 = 0.f, a3 = 0.f;
    int j = s;
    for (; j + 3 < e; j += 4) {
        a0 += g_norm[j]     * h[(size_t)g_src[j]     * FIN + t];
        a1 += g_norm[j + 1] * h[(size_t)g_src[j + 1] * FIN + t];
        a2 += g_norm[j + 2] * h[(size_t)g_src[j + 2] * FIN + t];
        a3 += g_norm[j + 3] * h[(size_t)g_src[j + 3] * FIN + t];
    }
    for (; j < e; j++) a0 += g_norm[j] * h[(size_t)g_src[j] * FIN + t];
    split_store((a0 + a1) + (a2 + a3), (size_t)node * FIN + t);
}
__global__ void k_agg_h() {
    int node = blockIdx.x, t = threadIdx.x;         // 256 threads
    int s = g_rowptr[node], e = g_rowptr[node + 1];
    float di = g_dinv[node];
    float a0 = di * di * g_bufA[(size_t)node * FH + t], a1 = 0.f, a2 = 0.f, a3 = 0.f;
    int j = s;
    for (; j + 3 < e; j += 4) {
        a0 += g_norm[j]     * g_bufA[(size_t)g_src[j]     * FH + t];
        a1 += g_norm[j + 1] * g_bufA[(size_t)g_src[j + 1] * FH + t];
        a2 += g_norm[j + 2] * g_bufA[(size_t)g_src[j + 2] * FH + t];
        a3 += g_norm[j + 3] * g_bufA[(size_t)g_src[j + 3] * FH + t];
    }
    for (; j < e; j++) a0 += g_norm[j] * g_bufA[(size_t)g_src[j] * FH + t];
    split_store((a0 + a1) + (a2 + a3), (size_t)node * FH + t);
}

// ================= weight conversion: W [K,256] -> Whi/Wlo [256,K] ==========
__global__ void k_convW(const float* __restrict__ W, int K) {
    int idx = blockIdx.x * blockDim.x + threadIdx.x;
    if (idx >= 256 * K) return;
    int n = idx / K, k = idx - n * K;
    float w = W[(size_t)k * FH + n];
    __nv_bfloat16 hi = __float2bfloat16(w);
    g_Whi[idx] = hi;
    g_Wlo[idx] = __float2bfloat16(w - __bfloat162float(hi));
}

// ================= HMMA GEMM: g_bufA = relu([Ahi|Ahi|Alo] @ [Whi;Wlo;Whi]^T)
// CTA tile 128x128, BK=64, 8 warps (2x4), warp tile 64x32, double-buffered.
#define SMEM_TOTAL 65536
__global__ void __launch_bounds__(256, 1) k_mma(int K) {
    extern __shared__ char smem[];
    uint32_t sb = smem_u32(smem);
    int tid = threadIdx.x, lane = tid & 31, wid = tid >> 5;
    int wm = wid >> 2, wn = wid & 3;               // 2 x 4 warp grid
    int m0 = blockIdx.x * 128, bn = blockIdx.y * 128;
    int cpp = K >> 6, nch = 3 * cpp;
    const uint32_t aoff[2] = {0u, 32768u};
    const uint32_t boff[2] = {16384u, 49152u};

    float acc[4][4][4];
    #pragma unroll
    for (int i = 0; i < 4; i++)
        #pragma unroll
        for (int j = 0; j < 4; j++)
            #pragma unroll
            for (int q = 0; q < 4; q++) acc[i][j][q] = 0.f;

    auto issue = [&](int c) {
        int pass = c / cpp;
        int k0 = (c - pass * cpp) << 6;
        const __nv_bfloat16* As = (pass < 2) ? g_Ahi : g_Alo;
        const __nv_bfloat16* Bs = (pass == 1) ? g_Wlo : g_Whi;
        int b = c & 1;
        #pragma unroll
        for (int i = 0; i < 4; i++) {
            int idx = tid + i * 256;
            int r = idx >> 3, v = idx & 7;
            int gr = m0 + r;
            int ok = gr < NODES;
            const __nv_bfloat16* src = As + (size_t)(ok ? gr : 0) * K + k0 + v * 8;
            uint32_t dst = sb + aoff[b] + sw128((uint32_t)(r * 128 + v * 16));
            unsigned long long gs = (unsigned long long)__cvta_generic_to_global((void*)src);
            int sz = ok ? 16 : 0;
            asm volatile("cp.async.cg.shared.global [%0], [%1], 16, %2;" :: "r"(dst), "l"(gs), "r"(sz));
        }
        #pragma unroll
        for (int i = 0; i < 4; i++) {
            int idx = tid + i * 256;
            int r = idx >> 3, v = idx & 7;
            const __nv_bfloat16* src = Bs + (size_t)(bn + r) * K + k0 + v * 8;
            uint32_t dst = sb + boff[b] + sw128((uint32_t)(r * 128 + v * 16));
            unsigned long long gs = (unsigned long long)__cvta_generic_to_global((void*)src);
            asm volatile("cp.async.cg.shared.global [%0], [%1], 16;" :: "r"(dst), "l"(gs));
        }
        asm volatile("cp.async.commit_group;" ::: "memory");
    };

    issue(0);

    // shared ldmatrix lane mapping (same for A and B tiles):
    // grp0: rows 0-7,k0-7 | grp1: rows 8-15,k0-7 | grp2: rows 0-7,k8-15 | grp3: rows 8-15,k8-15
    int grp = lane >> 3;
    int rr = (lane & 7) + ((grp & 1) << 3);
    int kof = (grp >= 2) ? 16 : 0;

    for (int c = 0; c < nch; c++) {
        int b = c & 1;
        if (c + 1 < nch) { issue(c + 1); asm volatile("cp.async.wait_group 1;" ::: "memory"); }
        else             { asm volatile("cp.async.wait_group 0;" ::: "memory"); }
        __syncthreads();
        uint32_t ab = sb + aoff[b], bb = sb + boff[b];
        #pragma unroll
        for (int kk = 0; kk < 4; kk++) {
            uint32_t a[4][4], bf[2][4];
            #pragma unroll
            for (int mt = 0; mt < 4; mt++) {
                uint32_t addr = ab + sw128((uint32_t)((wm * 64 + mt * 16 + rr) * 128 + kk * 32 + kof));
                asm volatile("ldmatrix.sync.aligned.m8n8.x4.shared.b16 {%0,%1,%2,%3}, [%4];"
                    : "=r"(a[mt][0]), "=r"(a[mt][1]), "=r"(a[mt][2]), "=r"(a[mt][3]) : "r"(addr));
            }
            #pragma unroll
            for (int p = 0; p < 2; p++) {
                uint32_t addr = bb + sw128((uint32_t)((wn * 32 + p * 16 + rr) * 128 + kk * 32 + kof));
                asm volatile("ldmatrix.sync.aligned.m8n8.x4.shared.b16 {%0,%1,%2,%3}, [%4];"
                    : "=r"(bf[p][0]), "=r"(bf[p][1]), "=r"(bf[p][2]), "=r"(bf[p][3]) : "r"(addr));
            }
            #pragma unroll
            for (int mt = 0; mt < 4; mt++)
                #pragma unroll
                for (int nt = 0; nt < 4; nt++) {
                    // B tile regs: [0]=n0-7/k0-7 [1]=n8-15/k0-7 [2]=n0-7/k8-15 [3]=n8-15/k8-15
                    uint32_t b0 = bf[nt >> 1][nt & 1];
                    uint32_t b1 = bf[nt >> 1][(nt & 1) + 2];
                    asm volatile("mma.sync.aligned.m16n8k16.row.col.f32.bf16.bf16.f32 "
                        "{%0,%1,%2,%3}, {%4,%5,%6,%7}, {%8,%9}, {%0,%1,%2,%3};"
                        : "+f"(acc[mt][nt][0]), "+f"(acc[mt][nt][1]),
                          "+f"(acc[mt][nt][2]), "+f"(acc[mt][nt][3])
                        : "r"(a[mt][0]), "r"(a[mt][1]), "r"(a[mt][2]), "r"(a[mt][3]),
                          "r"(b0), "r"(b1));
                }
        }
        __syncthreads();
    }

    // epilogue: relu + fp32 store
    int colb = bn + wn * 32 + 2 * (lane & 3);
    #pragma unroll
    for (int mt = 0; mt < 4; mt++) {
        int row = m0 + wm * 64 + mt * 16 + (lane >> 2);
        #pragma unroll
        for (int nt = 0; nt < 4; nt++) {
            if (row < NODES) {
                float2 v = make_float2(fmaxf(acc[mt][nt][0], 0.f), fmaxf(acc[mt][nt][1], 0.f));
                *(float2*)(g_bufA + (size_t)row * FH + colb + nt * 8) = v;
            }
            if (row + 8 < NODES) {
                float2 v = make_float2(fmaxf(acc[mt][nt][2], 0.f), fmaxf(acc[mt][nt][3], 0.f));
                *(float2*)(g_bufA + (size_t)(row + 8) * FH + colb + nt * 8) = v;
            }
        }
    }
}

// ================= pooling ==================================================
__global__ void k_gcount(const void* __restrict__ batch) {
    int i = blockIdx.x * blockDim.x + threadIdx.x;
    if (i < NODES) atomicAdd(&g_gcount[load_idx(batch, i)], 1);
}
__global__ void k_scan_graphs() {
    __shared__ int sm[NGRAPH];
    int t = threadIdx.x;
    int v = g_gcount[t];
    sm[t] = v;
    __syncthreads();
    for (int off = 1; off < NGRAPH; off <<= 1) {
        int add = (t >= off) ? sm[t - off] : 0;
        __syncthreads();
        sm[t] += add;
        __syncthreads();
    }
    g_gstart[t] = sm[t] - v;
    if (t == NGRAPH - 1) g_gstart[NGRAPH] = sm[t];
}
__global__ void k_pool() {
    int g = blockIdx.x, t = threadIdx.x;
    int s = g_gstart[g], e = g_gstart[g + 1];
    float sum = 0.f;
    for (int i = s; i < e; i++) sum += g_bufA[(size_t)i * FH + t];
    int cnt = e - s;
    g_pooled[g * FH + t] = sum / (float)(cnt > 0 ? cnt : 1);
}

// ================= MLP head =================================================
__global__ void k_head(const float* __restrict__ Wm1, const float* __restrict__ bm1,
                       const float* __restrict__ Wm2, const float* __restrict__ bm2,
                       float* __restrict__ out) {
    __shared__ float sp[FH];
    __shared__ float sh[FH];
    __shared__ float sl[FOUT];
    __shared__ float s_m, s_lse;
    int g = blockIdx.x, t = threadIdx.x;
    sp[t] = g_pooled[g * FH + t];
    __syncthreads();
    float acc = bm1[t];
    #pragma unroll 8
    for (int k = 0; k < FH; k++) acc += sp[k] * Wm1[k * FH + t];
    sh[t] = acc > 0.f ? acc : 0.f;
    __syncthreads();
    if (t < FOUT) {
        float a = bm2[t];
        for (int k = 0; k < FH; k++) a += sh[k] * Wm2[k * FOUT + t];
        sl[t] = a;
    }
    __syncthreads();
    if (t == 0) {
        float m = sl[0];
        for (int o = 1; o < FOUT; o++) m = fmaxf(m, sl[o]);
        float s = 0.f;
        for (int o = 0; o < FOUT; o++) s += expf(sl[o] - m);
        s_m = m; s_lse = logf(s);
    }
    __syncthreads();
    if (t < FOUT) {
        float v = sl[t];
        out[g * FOUT + t]                     = v - s_m - s_lse;
        out[NGRAPH * FOUT + g * FOUT + t]     = 1.0f / (1.0f + expf(-v));
        out[2 * NGRAPH * FOUT + g * FOUT + t] = v;
    }
}

// ================= launch ===================================================
extern "C" void kernel_launch(void* const* d_in, const int* in_sizes, int n_in,
                              void* d_out, int out_size) {
    const float* x     = (const float*)d_in[0];
    const void*  ei    = d_in[1];
    const void*  batch = d_in[3];
    const float* W0  = (const float*)d_in[4];
    const float* W1  = (const float*)d_in[5];
    const float* W2  = (const float*)d_in[6];
    const float* Wm1 = (const float*)d_in[7];
    const float* bm1 = (const float*)d_in[8];
    const float* Wm2 = (const float*)d_in[9];
    const float* bm2 = (const float*)d_in[10];
    float* out = (float*)d_out;

    cudaFuncSetAttribute(k_mma, cudaFuncAttributeMaxDynamicSharedMemorySize, SMEM_TOTAL);

    // ---- graph structure
    k_detect<<<1, 256>>>((const int*)ei);
    k_zero<<<(NODES + 255) / 256, 256>>>();
    k_deg<<<(EDGES + 255) / 256, 256>>>(ei);
    k_dinv<<<(NODES + 255) / 256, 256>>>();
    k_scan_rowptr<<<1, 1024>>>();
    k_scatter<<<(EDGES + 255) / 256, 256>>>(ei);

    dim3 mg((NODES + 127) / 128, 2);   // 391 x 2

    // ---- layer 0
    k_agg_x<<<NODES, FIN>>>(x);
    k_convW<<<(256 * FIN + 255) / 256, 256>>>(W0, FIN);
    k_mma<<<mg, 256, SMEM_TOTAL>>>(FIN);
    // ---- layer 1
    k_agg_h<<<NODES, FH>>>();
    k_convW<<<(256 * FH + 255) / 256, 256>>>(W1, FH);
    k_mma<<<mg, 256, SMEM_TOTAL>>>(FH);
    // ---- layer 2
    k_agg_h<<<NODES, FH>>>();
    k_convW<<<(256 * FH + 255) / 256, 256>>>(W2, FH);
    k_mma<<<mg, 256, SMEM_TOTAL>>>(FH);

    // ---- pool + head
    k_gcount<<<(NODES + 255) / 256, 256>>>(batch);
    k_scan_graphs<<<1, NGRAPH>>>();
    k_pool<<<NGRAPH, FH>>>();
    k_head<<<NGRAPH, FH>>>(Wm1, bm1, Wm2, bm2, out);
}

// round 7
// speedup vs baseline: 1.9693x; 1.5193x over previous
#include <cuda_runtime.h>
#include <cuda_bf16.h>
#include <math.h>
#include <stdint.h>

// Problem constants (fixed by the reference)
#define NODES 50000
#define EDGES 800000
#define FIN   128
#define FH    256
#define FOUT  10
#define NGRAPH 128

__device__ __forceinline__ uint32_t smem_u32(const void* p) {
    uint32_t a;
    asm("{ .reg .u64 t; cvta.to.shared.u64 t, %1; cvt.u32.u64 %0, t; }" : "=r"(a) : "l"(p));
    return a;
}
__device__ __forceinline__ uint32_t sw128(uint32_t off) { return off ^ ((off >> 3) & 0x70); }

struct EdgeRec { int src; float norm; };

// ================= scratch (device globals; no runtime allocation) ==========
__device__ float          g_bufA[(size_t)NODES * FH];     // h (fp32)
__device__ __nv_bfloat16  g_Ahi[(size_t)NODES * FH];      // agg output, bf16 high
__device__ __nv_bfloat16  g_Alo[(size_t)NODES * FH];      // agg output, bf16 low
__device__ __nv_bfloat16  g_Whi[FH * FH];                 // weight, [N=256][K] bf16 high
__device__ __nv_bfloat16  g_Wlo[FH * FH];
__device__ float   g_dinv[NODES];
__device__ int     g_deg[NODES];
__device__ int     g_rowptr[NODES + 1];
__device__ int     g_cursor[NODES];
__device__ EdgeRec g_edge[EDGES];
__device__ float   g_pooled[NGRAPH * FH];
__device__ int     g_gcount[NGRAPH];
__device__ int     g_gstart[NGRAPH + 1];
__device__ int     g_is64;

// ================= dtype probe =============================================
__global__ void k_detect(const int* __restrict__ ei32) {
    __shared__ int nonzero;
    if (threadIdx.x == 0) nonzero = 0;
    __syncthreads();
    int stride = (2 * EDGES) / 256;
    int pos = threadIdx.x * stride + 1;
    if (ei32[pos | 1] != 0) atomicOr(&nonzero, 1);
    __syncthreads();
    if (threadIdx.x == 0) g_is64 = nonzero ? 0 : 1;
}
__device__ __forceinline__ int load_idx(const void* p, size_t i) {
    return g_is64 ? (int)((const long long*)p)[i] : ((const int*)p)[i];
}

// ================= setup ====================================================
__global__ void k_zero() {
    int i = blockIdx.x * blockDim.x + threadIdx.x;
    if (i < NODES) { g_deg[i] = 0; g_cursor[i] = 0; }
    if (i < NGRAPH) g_gcount[i] = 0;
}
__global__ void k_deg(const void* __restrict__ ei) {
    int e = blockIdx.x * blockDim.x + threadIdx.x;
    if (e >= EDGES) return;
    atomicAdd(&g_deg[load_idx(ei, (size_t)EDGES + e)], 1);
}
__global__ void k_dinv() {
    int i = blockIdx.x * blockDim.x + threadIdx.x;
    if (i < NODES) g_dinv[i] = rsqrtf((float)g_deg[i] + 1.0f);
}
// shuffle-based exclusive scan of g_deg -> g_rowptr, single block 1024 threads
__global__ void k_scan_rowptr() {
    __shared__ int wsum[32];
    __shared__ int carry;
    int t = threadIdx.x, lane = t & 31, w = t >> 5;
    if (t == 0) carry = 0;
    __syncthreads();
    for (int base = 0; base < NODES; base += 1024) {
        int i = base + t;
        int v = (i < NODES) ? g_deg[i] : 0;
        int x = v;
        #pragma unroll
        for (int off = 1; off < 32; off <<= 1) {
            int y = __shfl_up_sync(0xFFFFFFFFu, x, off);
            if (lane >= off) x += y;
        }
        if (lane == 31) wsum[w] = x;
        __syncthreads();
        if (w == 0) {
            int s = wsum[lane];
            #pragma unroll
            for (int off = 1; off < 32; off <<= 1) {
                int y = __shfl_up_sync(0xFFFFFFFFu, s, off);
                if (lane >= off) s += y;
            }
            wsum[lane] = s;
        }
        __syncthreads();
        int woff = (w > 0) ? wsum[w - 1] : 0;
        if (i < NODES) g_rowptr[i] = carry + woff + x - v;
        __syncthreads();
        if (t == 0) carry += wsum[31];
        __syncthreads();
    }
    if (t == 0) g_rowptr[NODES] = carry;
}
__global__ void k_scatter(const void* __restrict__ ei) {
    int e = blockIdx.x * blockDim.x + threadIdx.x;
    if (e >= EDGES) return;
    int row = load_idx(ei, e);
    int col = load_idx(ei, (size_t)EDGES + e);
    int pos = atomicAdd(&g_cursor[col], 1);
    EdgeRec r; r.src = row; r.norm = g_dinv[row] * g_dinv[col];
    g_edge[g_rowptr[col] + pos] = r;
}

// ================= aggregation (float4, writes bf16 hi/lo staging) ==========
__device__ __forceinline__ void split_store4(float4 v, size_t idx) {
    // idx in elements, multiple of 4
    __nv_bfloat16 h0 = __float2bfloat16(v.x), h1 = __float2bfloat16(v.y);
    __nv_bfloat16 h2 = __float2bfloat16(v.z), h3 = __float2bfloat16(v.w);
    __nv_bfloat162* hp = (__nv_bfloat162*)(g_Ahi + idx);
    hp[0] = __nv_bfloat162{h0, h1}; hp[1] = __nv_bfloat162{h2, h3};
    __nv_bfloat16 l0 = __float2bfloat16(v.x - __bfloat162float(h0));
    __nv_bfloat16 l1 = __float2bfloat16(v.y - __bfloat162float(h1));
    __nv_bfloat16 l2 = __float2bfloat16(v.z - __bfloat162float(h2));
    __nv_bfloat16 l3 = __float2bfloat16(v.w - __bfloat162float(h3));
    __nv_bfloat162* lp = (__nv_bfloat162*)(g_Alo + idx);
    lp[0] = __nv_bfloat162{l0, l1}; lp[1] = __nv_bfloat162{l2, l3};
}
// layer 0: x [N,128]; 32 threads/node, 8 nodes per 256-thread block
__global__ void __launch_bounds__(256) k_agg_x(const float* __restrict__ h) {
    int node = blockIdx.x * 8 + (threadIdx.x >> 5);
    if (node >= NODES) return;
    int c = (threadIdx.x & 31) * 4;
    int s = g_rowptr[node], e = g_rowptr[node + 1];
    float di = g_dinv[node];
    float4 self = *(const float4*)(h + (size_t)node * FIN + c);
    float4 acc = make_float4(di * di * self.x, di * di * self.y,
                             di * di * self.z, di * di * self.w);
    int j = s;
    for (; j + 1 < e; j += 2) {
        EdgeRec e0 = g_edge[j], e1 = g_edge[j + 1];
        float4 v0 = *(const float4*)(h + (size_t)e0.src * FIN + c);
        float4 v1 = *(const float4*)(h + (size_t)e1.src * FIN + c);
        acc.x += e0.norm * v0.x + e1.norm * v1.x;
        acc.y += e0.norm * v0.y + e1.norm * v1.y;
        acc.z += e0.norm * v0.z + e1.norm * v1.z;
        acc.w += e0.norm * v0.w + e1.norm * v1.w;
    }
    if (j < e) {
        EdgeRec e0 = g_edge[j];
        float4 v0 = *(const float4*)(h + (size_t)e0.src * FIN + c);
        acc.x += e0.norm * v0.x; acc.y += e0.norm * v0.y;
        acc.z += e0.norm * v0.z; acc.w += e0.norm * v0.w;
    }
    split_store4(acc, (size_t)node * FIN + c);
}
// layers 1,2: g_bufA [N,256]; 64 threads/node, 4 nodes per 256-thread block
__global__ void __launch_bounds__(256) k_agg_h() {
    int node = blockIdx.x * 4 + (threadIdx.x >> 6);
    if (node >= NODES) return;
    int c = (threadIdx.x & 63) * 4;
    int s = g_rowptr[node], e = g_rowptr[node + 1];
    float di = g_dinv[node];
    float4 self = *(const float4*)(g_bufA + (size_t)node * FH + c);
    float4 acc = make_float4(di * di * self.x, di * di * self.y,
                             di * di * self.z, di * di * self.w);
    int j = s;
    for (; j + 1 < e; j += 2) {
        EdgeRec e0 = g_edge[j], e1 = g_edge[j + 1];
        float4 v0 = *(const float4*)(g_bufA + (size_t)e0.src * FH + c);
        float4 v1 = *(const float4*)(g_bufA + (size_t)e1.src * FH + c);
        acc.x += e0.norm * v0.x + e1.norm * v1.x;
        acc.y += e0.norm * v0.y + e1.norm * v1.y;
        acc.z += e0.norm * v0.z + e1.norm * v1.z;
        acc.w += e0.norm * v0.w + e1.norm * v1.w;
    }
    if (j < e) {
        EdgeRec e0 = g_edge[j];
        float4 v0 = *(const float4*)(g_bufA + (size_t)e0.src * FH + c);
        acc.x += e0.norm * v0.x; acc.y += e0.norm * v0.y;
        acc.z += e0.norm * v0.z; acc.w += e0.norm * v0.w;
    }
    split_store4(acc, (size_t)node * FH + c);
}

// ================= weight conversion: W [K,256] -> Whi/Wlo [256,K] ==========
__global__ void k_convW(const float* __restrict__ W, int K) {
    int idx = blockIdx.x * blockDim.x + threadIdx.x;
    if (idx >= 256 * K) return;
    int n = idx / K, k = idx - n * K;
    float w = W[(size_t)k * FH + n];
    __nv_bfloat16 hi = __float2bfloat16(w);
    g_Whi[idx] = hi;
    g_Wlo[idx] = __float2bfloat16(w - __bfloat162float(hi));
}

// ================= HMMA GEMM: g_bufA = relu([Ahi|Ahi|Alo] @ [Whi;Wlo;Whi]^T)
// CTA tile 128x128, BK=64, 8 warps (2x4), warp tile 64x32, double-buffered.
#define SMEM_TOTAL 65536
__global__ void __launch_bounds__(256, 2) k_mma(int K) {
    extern __shared__ char smem[];
    uint32_t sb = smem_u32(smem);
    int tid = threadIdx.x, lane = tid & 31, wid = tid >> 5;
    int wm = wid >> 2, wn = wid & 3;               // 2 x 4 warp grid
    int m0 = blockIdx.x * 128, bn = blockIdx.y * 128;
    int cpp = K >> 6, nch = 3 * cpp;
    const uint32_t aoff[2] = {0u, 32768u};
    const uint32_t boff[2] = {16384u, 49152u};

    float acc[4][4][4];
    #pragma unroll
    for (int i = 0; i < 4; i++)
        #pragma unroll
        for (int j = 0; j < 4; j++)
            #pragma unroll
            for (int q = 0; q < 4; q++) acc[i][j][q] = 0.f;

    auto issue = [&](int c) {
        int pass = c / cpp;
        int k0 = (c - pass * cpp) << 6;
        const __nv_bfloat16* As = (pass < 2) ? g_Ahi : g_Alo;
        const __nv_bfloat16* Bs = (pass == 1) ? g_Wlo : g_Whi;
        int b = c & 1;
        #pragma unroll
        for (int i = 0; i < 4; i++) {
            int idx = tid + i * 256;
            int r = idx >> 3, v = idx & 7;
            int gr = m0 + r;
            int ok = gr < NODES;
            const __nv_bfloat16* src = As + (size_t)(ok ? gr : 0) * K + k0 + v * 8;
            uint32_t dst = sb + aoff[b] + sw128((uint32_t)(r * 128 + v * 16));
            unsigned long long gs = (unsigned long long)__cvta_generic_to_global((void*)src);
            int sz = ok ? 16 : 0;
            asm volatile("cp.async.cg.shared.global [%0], [%1], 16, %2;" :: "r"(dst), "l"(gs), "r"(sz));
        }
        #pragma unroll
        for (int i = 0; i < 4; i++) {
            int idx = tid + i * 256;
            int r = idx >> 3, v = idx & 7;
            const __nv_bfloat16* src = Bs + (size_t)(bn + r) * K + k0 + v * 8;
            uint32_t dst = sb + boff[b] + sw128((uint32_t)(r * 128 + v * 16));
            unsigned long long gs = (unsigned long long)__cvta_generic_to_global((void*)src);
            asm volatile("cp.async.cg.shared.global [%0], [%1], 16;" :: "r"(dst), "l"(gs));
        }
        asm volatile("cp.async.commit_group;" ::: "memory");
    };

    issue(0);

    int grp = lane >> 3;
    int rr = (lane & 7) + ((grp & 1) << 3);
    int kof = (grp >= 2) ? 16 : 0;

    for (int c = 0; c < nch; c++) {
        int b = c & 1;
        if (c + 1 < nch) { issue(c + 1); asm volatile("cp.async.wait_group 1;" ::: "memory"); }
        else             { asm volatile("cp.async.wait_group 0;" ::: "memory"); }
        __syncthreads();
        uint32_t ab = sb + aoff[b], bb = sb + boff[b];
        #pragma unroll
        for (int kk = 0; kk < 4; kk++) {
            uint32_t a[4][4], bf[2][4];
            #pragma unroll
            for (int mt = 0; mt < 4; mt++) {
                uint32_t addr = ab + sw128((uint32_t)((wm * 64 + mt * 16 + rr) * 128 + kk * 32 + kof));
                asm volatile("ldmatrix.sync.aligned.m8n8.x4.shared.b16 {%0,%1,%2,%3}, [%4];"
                    : "=r"(a[mt][0]), "=r"(a[mt][1]), "=r"(a[mt][2]), "=r"(a[mt][3]) : "r"(addr));
            }
            #pragma unroll
            for (int p = 0; p < 2; p++) {
                uint32_t addr = bb + sw128((uint32_t)((wn * 32 + p * 16 + rr) * 128 + kk * 32 + kof));
                asm volatile("ldmatrix.sync.aligned.m8n8.x4.shared.b16 {%0,%1,%2,%3}, [%4];"
                    : "=r"(bf[p][0]), "=r"(bf[p][1]), "=r"(bf[p][2]), "=r"(bf[p][3]) : "r"(addr));
            }
            #pragma unroll
            for (int mt = 0; mt < 4; mt++)
                #pragma unroll
                for (int nt = 0; nt < 4; nt++) {
                    uint32_t b0 = bf[nt >> 1][nt & 1];
                    uint32_t b1 = bf[nt >> 1][(nt & 1) + 2];
                    asm volatile("mma.sync.aligned.m16n8k16.row.col.f32.bf16.bf16.f32 "
                        "{%0,%1,%2,%3}, {%4,%5,%6,%7}, {%8,%9}, {%0,%1,%2,%3};"
                        : "+f"(acc[mt][nt][0]), "+f"(acc[mt][nt][1]),
                          "+f"(acc[mt][nt][2]), "+f"(acc[mt][nt][3])
                        : "r"(a[mt][0]), "r"(a[mt][1]), "r"(a[mt][2]), "r"(a[mt][3]),
                          "r"(b0), "r"(b1));
                }
        }
        __syncthreads();
    }

    // epilogue: relu + fp32 store
    int colb = bn + wn * 32 + 2 * (lane & 3);
    #pragma unroll
    for (int mt = 0; mt < 4; mt++) {
        int row = m0 + wm * 64 + mt * 16 + (lane >> 2);
        #pragma unroll
        for (int nt = 0; nt < 4; nt++) {
            if (row < NODES) {
                float2 v = make_float2(fmaxf(acc[mt][nt][0], 0.f), fmaxf(acc[mt][nt][1], 0.f));
                *(float2*)(g_bufA + (size_t)row * FH + colb + nt * 8) = v;
            }
            if (row + 8 < NODES) {
                float2 v = make_float2(fmaxf(acc[mt][nt][2], 0.f), fmaxf(acc[mt][nt][3], 0.f));
                *(float2*)(g_bufA + (size_t)(row + 8) * FH + colb + nt * 8) = v;
            }
        }
    }
}

// ================= pooling ==================================================
__global__ void k_gcount(const void* __restrict__ batch) {
    int i = blockIdx.x * blockDim.x + threadIdx.x;
    if (i < NODES) atomicAdd(&g_gcount[load_idx(batch, i)], 1);
}
__global__ void k_scan_graphs() {
    __shared__ int sm[NGRAPH];
    int t = threadIdx.x;
    int v = g_gcount[t];
    sm[t] = v;
    __syncthreads();
    for (int off = 1; off < NGRAPH; off <<= 1) {
        int add = (t >= off) ? sm[t - off] : 0;
        __syncthreads();
        sm[t] += add;
        __syncthreads();
    }
    g_gstart[t] = sm[t] - v;
    if (t == NGRAPH - 1) g_gstart[NGRAPH] = sm[t];
}
// block 256 = 64 cols(float4) x 4 row-groups
__global__ void k_pool() {
    __shared__ float4 red[4][64];
    int g = blockIdx.x;
    int t = threadIdx.x, cg = t & 63, rg = t >> 6;
    int c = cg * 4;
    int s = g_gstart[g], e = g_gstart[g + 1];
    float4 acc = make_float4(0.f, 0.f, 0.f, 0.f);
    for (int i = s + rg; i < e; i += 4) {
        float4 v = *(const float4*)(g_bufA + (size_t)i * FH + c);
        acc.x += v.x; acc.y += v.y; acc.z += v.z; acc.w += v.w;
    }
    red[rg][cg] = acc;
    __syncthreads();
    if (rg == 0) {
        float4 a0 = red[0][cg], a1 = red[1][cg], a2 = red[2][cg], a3 = red[3][cg];
        int cnt = e - s;
        float inv = 1.0f / (float)(cnt > 0 ? cnt : 1);
        float4 r = make_float4((a0.x + a1.x + a2.x + a3.x) * inv,
                               (a0.y + a1.y + a2.y + a3.y) * inv,
                               (a0.z + a1.z + a2.z + a3.z) * inv,
                               (a0.w + a1.w + a2.w + a3.w) * inv);
        *(float4*)(g_pooled + g * FH + c) = r;
    }
}

// ================= MLP head =================================================
__global__ void k_head(const float* __restrict__ Wm1, const float* __restrict__ bm1,
                       const float* __restrict__ Wm2, const float* __restrict__ bm2,
                       float* __restrict__ out) {
    __shared__ float sp[FH];
    __shared__ float sh[FH];
    __shared__ float sl[FOUT];
    __shared__ float s_m, s_lse;
    int g = blockIdx.x, t = threadIdx.x;
    sp[t] = g_pooled[g * FH + t];
    __syncthreads();
    float acc = bm1[t];
    #pragma unroll 8
    for (int k = 0; k < FH; k++) acc += sp[k] * Wm1[k * FH + t];
    sh[t] = acc > 0.f ? acc : 0.f;
    __syncthreads();
    if (t < FOUT) {
        float a = bm2[t];
        for (int k = 0; k < FH; k++) a += sh[k] * Wm2[k * FOUT + t];
        sl[t] = a;
    }
    __syncthreads();
    if (t == 0) {
        float m = sl[0];
        for (int o = 1; o < FOUT; o++) m = fmaxf(m, sl[o]);
        float s = 0.f;
        for (int o = 0; o < FOUT; o++) s += expf(sl[o] - m);
        s_m = m; s_lse = logf(s);
    }
    __syncthreads();
    if (t < FOUT) {
        float v = sl[t];
        out[g * FOUT + t]                     = v - s_m - s_lse;
        out[NGRAPH * FOUT + g * FOUT + t]     = 1.0f / (1.0f + expf(-v));
        out[2 * NGRAPH * FOUT + g * FOUT + t] = v;
    }
}

// ================= launch ===================================================
extern "C" void kernel_launch(void* const* d_in, const int* in_sizes, int n_in,
                              void* d_out, int out_size) {
    const float* x     = (const float*)d_in[0];
    const void*  ei    = d_in[1];
    const void*  batch = d_in[3];
    const float* W0  = (const float*)d_in[4];
    const float* W1  = (const float*)d_in[5];
    const float* W2  = (const float*)d_in[6];
    const float* Wm1 = (const float*)d_in[7];
    const float* bm1 = (const float*)d_in[8];
    const float* Wm2 = (const float*)d_in[9];
    const float* bm2 = (const float*)d_in[10];
    float* out = (float*)d_out;

    cudaFuncSetAttribute(k_mma, cudaFuncAttributeMaxDynamicSharedMemorySize, SMEM_TOTAL);

    // ---- graph structure
    k_detect<<<1, 256>>>((const int*)ei);
    k_zero<<<(NODES + 255) / 256, 256>>>();
    k_deg<<<(EDGES + 255) / 256, 256>>>(ei);
    k_dinv<<<(NODES + 255) / 256, 256>>>();
    k_scan_rowptr<<<1, 1024>>>();
    k_scatter<<<(EDGES + 255) / 256, 256>>>(ei);

    dim3 mg((NODES + 127) / 128, 2);   // 391 x 2

    // ---- layer 0
    k_agg_x<<<(NODES + 7) / 8, 256>>>(x);
    k_convW<<<(256 * FIN + 255) / 256, 256>>>(W0, FIN);
    k_mma<<<mg, 256, SMEM_TOTAL>>>(FIN);
    // ---- layer 1
    k_agg_h<<<(NODES + 3) / 4, 256>>>();
    k_convW<<<(256 * FH + 255) / 256, 256>>>(W1, FH);
    k_mma<<<mg, 256, SMEM_TOTAL>>>(FH);
    // ---- layer 2
    k_agg_h<<<(NODES + 3) / 4, 256>>>();
    k_convW<<<(256 * FH + 255) / 256, 256>>>(W2, FH);
    k_mma<<<mg, 256, SMEM_TOTAL>>>(FH);

    // ---- pool + head
    k_gcount<<<(NODES + 255) / 256, 256>>>(batch);
    k_scan_graphs<<<1, NGRAPH>>>();
    k_pool<<<NGRAPH, 256>>>();
    k_head<<<NGRAPH, FH>>>(Wm1, bm1, Wm2, bm2, out);
}

// round 8
// speedup vs baseline: 2.0093x; 1.0203x over previous
#include <cuda_runtime.h>
#include <cuda_bf16.h>
#include <math.h>
#include <stdint.h>

#define NODES 50000
#define EDGES 800000
#define FIN   128
#define FH    256
#define FOUT  10
#define NGRAPH 128

__device__ __forceinline__ uint32_t smem_u32(const void* p) {
    uint32_t a;
    asm("{ .reg .u64 t; cvta.to.shared.u64 t, %1; cvt.u32.u64 %0, t; }" : "=r"(a) : "l"(p));
    return a;
}
__device__ __forceinline__ uint32_t sw128(uint32_t off) { return off ^ ((off >> 3) & 0x70); }

struct EdgeRec { int src; float norm; };

// ================= scratch ==================================================
__device__ float          g_bufA[(size_t)NODES * FH];
__device__ __nv_bfloat16  g_Ahi[(size_t)NODES * FH];
__device__ __nv_bfloat16  g_Alo[(size_t)NODES * FH];
__device__ __nv_bfloat16  g_Whi0[FH * FIN];
__device__ __nv_bfloat16  g_Wlo0[FH * FIN];
__device__ __nv_bfloat16  g_Whi1[FH * FH];
__device__ __nv_bfloat16  g_Wlo1[FH * FH];
__device__ __nv_bfloat16  g_Whi2[FH * FH];
__device__ __nv_bfloat16  g_Wlo2[FH * FH];
__device__ float   g_dinv[NODES];
__device__ int     g_deg[NODES];
__device__ int     g_rowptr[NODES + 1];
__device__ int     g_cursor[NODES];
__device__ EdgeRec g_edge[EDGES];
__device__ float   g_pooled[NGRAPH * FH];
__device__ int     g_gcount[NGRAPH];
__device__ int     g_gstart[NGRAPH + 1];
__device__ int     g_is64;

// ================= dtype probe =============================================
__global__ void k_detect(const int* __restrict__ ei32) {
    __shared__ int nonzero;
    if (threadIdx.x == 0) nonzero = 0;
    __syncthreads();
    int stride = (2 * EDGES) / 256;
    int pos = threadIdx.x * stride + 1;
    if (ei32[pos | 1] != 0) atomicOr(&nonzero, 1);
    __syncthreads();
    if (threadIdx.x == 0) g_is64 = nonzero ? 0 : 1;
}
__device__ __forceinline__ int load_idx(const void* p, size_t i) {
    return g_is64 ? (int)((const long long*)p)[i] : ((const int*)p)[i];
}

// ================= setup ====================================================
__global__ void k_zero() {
    int i = blockIdx.x * blockDim.x + threadIdx.x;
    if (i < NODES) { g_deg[i] = 0; g_cursor[i] = 0; }
    if (i < NGRAPH) g_gcount[i] = 0;
}
// fused: degree histogram (edges) + graph-size histogram (batch)
__global__ void k_hist(const void* __restrict__ ei, const void* __restrict__ batch) {
    int i = blockIdx.x * blockDim.x + threadIdx.x;
    if (i < EDGES) atomicAdd(&g_deg[load_idx(ei, (size_t)EDGES + i)], 1);
    if (i < NODES) atomicAdd(&g_gcount[load_idx(batch, i)], 1);
}
// fused: exclusive scan of deg -> rowptr, dinv = rsqrt(deg+1), graph scan
__global__ void k_scan() {
    __shared__ int wsum[32];
    __shared__ int carry;
    __shared__ int gs[NGRAPH], gv[NGRAPH];
    int t = threadIdx.x, lane = t & 31, w = t >> 5;
    if (t == 0) carry = 0;
    __syncthreads();
    for (int base = 0; base < NODES; base += 1024) {
        int i = base + t;
        int v = 0;
        if (i < NODES) {
            v = g_deg[i];
            g_dinv[i] = rsqrtf((float)v + 1.0f);
        }
        int x = v;
        #pragma unroll
        for (int off = 1; off < 32; off <<= 1) {
            int y = __shfl_up_sync(0xFFFFFFFFu, x, off);
            if (lane >= off) x += y;
        }
        if (lane == 31) wsum[w] = x;
        __syncthreads();
        if (w == 0) {
            int s = wsum[lane];
            #pragma unroll
            for (int off = 1; off < 32; off <<= 1) {
                int y = __shfl_up_sync(0xFFFFFFFFu, s, off);
                if (lane >= off) s += y;
            }
            wsum[lane] = s;
        }
        __syncthreads();
        int woff = (w > 0) ? wsum[w - 1] : 0;
        if (i < NODES) g_rowptr[i] = carry + woff + x - v;
        __syncthreads();
        if (t == 0) carry += wsum[31];
        __syncthreads();
    }
    if (t == 0) g_rowptr[NODES] = carry;
    // graph prefix
    if (t < NGRAPH) { gv[t] = g_gcount[t]; gs[t] = gv[t]; }
    __syncthreads();
    for (int off = 1; off < NGRAPH; off <<= 1) {
        int add = (t >= off && t < NGRAPH) ? gs[t - off] : 0;
        __syncthreads();
        if (t < NGRAPH) gs[t] += add;
        __syncthreads();
    }
    if (t < NGRAPH) {
        g_gstart[t] = gs[t] - gv[t];
        if (t == NGRAPH - 1) g_gstart[NGRAPH] = gs[t];
    }
}
__global__ void k_scatter(const void* __restrict__ ei) {
    int e = blockIdx.x * blockDim.x + threadIdx.x;
    if (e >= EDGES) return;
    int row = load_idx(ei, e);
    int col = load_idx(ei, (size_t)EDGES + e);
    int pos = atomicAdd(&g_cursor[col], 1);
    EdgeRec r; r.src = row; r.norm = g_dinv[row] * g_dinv[col];
    g_edge[g_rowptr[col] + pos] = r;
}

// ================= all-weights conversion (upfront, one launch) =============
__global__ void k_convAll(const float* __restrict__ W0, const float* __restrict__ W1,
                          const float* __restrict__ W2) {
    int idx = blockIdx.x * blockDim.x + threadIdx.x;
    float w;
    __nv_bfloat16 *hi, *lo;
    if (idx < 256 * FIN) {
        int n = idx / FIN, k = idx - n * FIN;
        w = W0[(size_t)k * FH + n]; hi = g_Whi0 + idx; lo = g_Wlo0 + idx;
    } else if (idx < 256 * FIN + 256 * FH) {
        int j = idx - 256 * FIN;
        int n = j / FH, k = j - n * FH;
        w = W1[(size_t)k * FH + n]; hi = g_Whi1 + j; lo = g_Wlo1 + j;
    } else if (idx < 256 * FIN + 2 * 256 * FH) {
        int j = idx - 256 * FIN - 256 * FH;
        int n = j / FH, k = j - n * FH;
        w = W2[(size_t)k * FH + n]; hi = g_Whi2 + j; lo = g_Wlo2 + j;
    } else return;
    __nv_bfloat16 h = __float2bfloat16(w);
    *hi = h;
    *lo = __float2bfloat16(w - __bfloat162float(h));
}

// ================= aggregation (float4, unroll 4, bf16 hi/lo out) ===========
__device__ __forceinline__ void split_store4(float4 v, size_t idx) {
    __nv_bfloat16 h0 = __float2bfloat16(v.x), h1 = __float2bfloat16(v.y);
    __nv_bfloat16 h2 = __float2bfloat16(v.z), h3 = __float2bfloat16(v.w);
    __nv_bfloat162* hp = (__nv_bfloat162*)(g_Ahi + idx);
    hp[0] = __nv_bfloat162{h0, h1}; hp[1] = __nv_bfloat162{h2, h3};
    __nv_bfloat16 l0 = __float2bfloat16(v.x - __bfloat162float(h0));
    __nv_bfloat16 l1 = __float2bfloat16(v.y - __bfloat162float(h1));
    __nv_bfloat16 l2 = __float2bfloat16(v.z - __bfloat162float(h2));
    __nv_bfloat16 l3 = __float2bfloat16(v.w - __bfloat162float(h3));
    __nv_bfloat162* lp = (__nv_bfloat162*)(g_Alo + idx);
    lp[0] = __nv_bfloat162{l0, l1}; lp[1] = __nv_bfloat162{l2, l3};
}
template <int D>
__device__ __forceinline__ void agg_body(const float* __restrict__ h, int node, int c) {
    int s = g_rowptr[node], e = g_rowptr[node + 1];
    float di = g_dinv[node];
    float4 self = *(const float4*)(h + (size_t)node * D + c);
    float4 acc = make_float4(di * di * self.x, di * di * self.y,
                             di * di * self.z, di * di * self.w);
    float4 acc2 = make_float4(0.f, 0.f, 0.f, 0.f);
    int j = s;
    for (; j + 3 < e; j += 4) {
        EdgeRec e0 = g_edge[j], e1 = g_edge[j + 1], e2 = g_edge[j + 2], e3 = g_edge[j + 3];
        float4 v0 = *(const float4*)(h + (size_t)e0.src * D + c);
        float4 v1 = *(const float4*)(h + (size_t)e1.src * D + c);
        float4 v2 = *(const float4*)(h + (size_t)e2.src * D + c);
        float4 v3 = *(const float4*)(h + (size_t)e3.src * D + c);
        acc.x  += e0.norm * v0.x + e1.norm * v1.x;
        acc.y  += e0.norm * v0.y + e1.norm * v1.y;
        acc.z  += e0.norm * v0.z + e1.norm * v1.z;
        acc.w  += e0.norm * v0.w + e1.norm * v1.w;
        acc2.x += e2.norm * v2.x + e3.norm * v3.x;
        acc2.y += e2.norm * v2.y + e3.norm * v3.y;
        acc2.z += e2.norm * v2.z + e3.norm * v3.z;
        acc2.w += e2.norm * v2.w + e3.norm * v3.w;
    }
    for (; j < e; j++) {
        EdgeRec e0 = g_edge[j];
        float4 v0 = *(const float4*)(h + (size_t)e0.src * D + c);
        acc.x += e0.norm * v0.x; acc.y += e0.norm * v0.y;
        acc.z += e0.norm * v0.z; acc.w += e0.norm * v0.w;
    }
    acc.x += acc2.x; acc.y += acc2.y; acc.z += acc2.z; acc.w += acc2.w;
    split_store4(acc, (size_t)node * D + c);
}
__global__ void __launch_bounds__(256) k_agg_x(const float* __restrict__ h) {
    int node = blockIdx.x * 8 + (threadIdx.x >> 5);
    if (node >= NODES) return;
    agg_body<FIN>(h, node, (threadIdx.x & 31) * 4);
}
__global__ void __launch_bounds__(256) k_agg_h() {
    int node = blockIdx.x * 4 + (threadIdx.x >> 6);
    if (node >= NODES) return;
    agg_body<FH>(g_bufA, node, (threadIdx.x & 63) * 4);
}

// ================= HMMA GEMM (3-stage pipeline) =============================
// CTA tile 128x128, BK=64, 8 warps (2x4), warp tile 64x32.
#define SMEM_TOTAL 98304
__global__ void __launch_bounds__(256, 2) k_mma(int K, int layer) {
    extern __shared__ char smem[];
    uint32_t sb = smem_u32(smem);
    int tid = threadIdx.x, lane = tid & 31, wid = tid >> 5;
    int wm = wid >> 2, wn = wid & 3;
    int m0 = blockIdx.x * 128, bn = blockIdx.y * 128;
    int cpp = K >> 6, nch = 3 * cpp;
    const __nv_bfloat16* Whi = (layer == 0) ? g_Whi0 : (layer == 1) ? g_Whi1 : g_Whi2;
    const __nv_bfloat16* Wlo = (layer == 0) ? g_Wlo0 : (layer == 1) ? g_Wlo1 : g_Wlo2;

    float acc[4][4][4];
    #pragma unroll
    for (int i = 0; i < 4; i++)
        #pragma unroll
        for (int j = 0; j < 4; j++)
            #pragma unroll
            for (int q = 0; q < 4; q++) acc[i][j][q] = 0.f;

    auto issue = [&](int c) {
        int pass = c / cpp;
        int k0 = (c - pass * cpp) << 6;
        const __nv_bfloat16* As = (pass < 2) ? g_Ahi : g_Alo;
        const __nv_bfloat16* Bs = (pass == 1) ? Wlo : Whi;
        uint32_t ao = (uint32_t)(c % 3) * 32768u;
        uint32_t bo = ao + 16384u;
        #pragma unroll
        for (int i = 0; i < 4; i++) {
            int idx = tid + i * 256;
            int r = idx >> 3, v = idx & 7;
            int gr = m0 + r;
            int ok = gr < NODES;
            const __nv_bfloat16* src = As + (size_t)(ok ? gr : 0) * K + k0 + v * 8;
            uint32_t dst = sb + ao + sw128((uint32_t)(r * 128 + v * 16));
            unsigned long long gs = (unsigned long long)__cvta_generic_to_global((void*)src);
            int sz = ok ? 16 : 0;
            asm volatile("cp.async.cg.shared.global [%0], [%1], 16, %2;" :: "r"(dst), "l"(gs), "r"(sz));
        }
        #pragma unroll
        for (int i = 0; i < 4; i++) {
            int idx = tid + i * 256;
            int r = idx >> 3, v = idx & 7;
            const __nv_bfloat16* src = Bs + (size_t)(bn + r) * K + k0 + v * 8;
            uint32_t dst = sb + bo + sw128((uint32_t)(r * 128 + v * 16));
            unsigned long long gs = (unsigned long long)__cvta_generic_to_global((void*)src);
            asm volatile("cp.async.cg.shared.global [%0], [%1], 16;" :: "r"(dst), "l"(gs));
        }
        asm volatile("cp.async.commit_group;" ::: "memory");
    };

    issue(0);
    issue(1);

    int grp = lane >> 3;
    int rr = (lane & 7) + ((grp & 1) << 3);
    int kof = (grp >= 2) ? 16 : 0;

    for (int c = 0; c < nch; c++) {
        if (c + 2 < nch) { issue(c + 2); asm volatile("cp.async.wait_group 2;" ::: "memory"); }
        else if (c + 1 < nch) { asm volatile("cp.async.wait_group 1;" ::: "memory"); }
        else { asm volatile("cp.async.wait_group 0;" ::: "memory"); }
        __syncthreads();
        uint32_t ab = sb + (uint32_t)(c % 3) * 32768u;
        uint32_t bb = ab + 16384u;
        #pragma unroll
        for (int kk = 0; kk < 4; kk++) {
            uint32_t a[4][4], bf[2][4];
            #pragma unroll
            for (int mt = 0; mt < 4; mt++) {
                uint32_t addr = ab + sw128((uint32_t)((wm * 64 + mt * 16 + rr) * 128 + kk * 32 + kof));
                asm volatile("ldmatrix.sync.aligned.m8n8.x4.shared.b16 {%0,%1,%2,%3}, [%4];"
                    : "=r"(a[mt][0]), "=r"(a[mt][1]), "=r"(a[mt][2]), "=r"(a[mt][3]) : "r"(addr));
            }
            #pragma unroll
            for (int p = 0; p < 2; p++) {
                uint32_t addr = bb + sw128((uint32_t)((wn * 32 + p * 16 + rr) * 128 + kk * 32 + kof));
                asm volatile("ldmatrix.sync.aligned.m8n8.x4.shared.b16 {%0,%1,%2,%3}, [%4];"
                    : "=r"(bf[p][0]), "=r"(bf[p][1]), "=r"(bf[p][2]), "=r"(bf[p][3]) : "r"(addr));
            }
            #pragma unroll
            for (int mt = 0; mt < 4; mt++)
                #pragma unroll
                for (int nt = 0; nt < 4; nt++) {
                    uint32_t b0 = bf[nt >> 1][nt & 1];
                    uint32_t b1 = bf[nt >> 1][(nt & 1) + 2];
                    asm volatile("mma.sync.aligned.m16n8k16.row.col.f32.bf16.bf16.f32 "
                        "{%0,%1,%2,%3}, {%4,%5,%6,%7}, {%8,%9}, {%0,%1,%2,%3};"
                        : "+f"(acc[mt][nt][0]), "+f"(acc[mt][nt][1]),
                          "+f"(acc[mt][nt][2]), "+f"(acc[mt][nt][3])
                        : "r"(a[mt][0]), "r"(a[mt][1]), "r"(a[mt][2]), "r"(a[mt][3]),
                          "r"(b0), "r"(b1));
                }
        }
        __syncthreads();
    }

    int colb = bn + wn * 32 + 2 * (lane & 3);
    #pragma unroll
    for (int mt = 0; mt < 4; mt++) {
        int row = m0 + wm * 64 + mt * 16 + (lane >> 2);
        #pragma unroll
        for (int nt = 0; nt < 4; nt++) {
            if (row < NODES) {
                float2 v = make_float2(fmaxf(acc[mt][nt][0], 0.f), fmaxf(acc[mt][nt][1], 0.f));
                *(float2*)(g_bufA + (size_t)row * FH + colb + nt * 8) = v;
            }
            if (row + 8 < NODES) {
                float2 v = make_float2(fmaxf(acc[mt][nt][2], 0.f), fmaxf(acc[mt][nt][3], 0.f));
                *(float2*)(g_bufA + (size_t)(row + 8) * FH + colb + nt * 8) = v;
            }
        }
    }
}

// ================= pooling ==================================================
__global__ void k_pool() {
    __shared__ float4 red[4][64];
    int g = blockIdx.x;
    int t = threadIdx.x, cg = t & 63, rg = t >> 6;
    int c = cg * 4;
    int s = g_gstart[g], e = g_gstart[g + 1];
    float4 acc = make_float4(0.f, 0.f, 0.f, 0.f);
    for (int i = s + rg; i < e; i += 4) {
        float4 v = *(const float4*)(g_bufA + (size_t)i * FH + c);
        acc.x += v.x; acc.y += v.y; acc.z += v.z; acc.w += v.w;
    }
    red[rg][cg] = acc;
    __syncthreads();
    if (rg == 0) {
        float4 a0 = red[0][cg], a1 = red[1][cg], a2 = red[2][cg], a3 = red[3][cg];
        int cnt = e - s;
        float inv = 1.0f / (float)(cnt > 0 ? cnt : 1);
        float4 r = make_float4((a0.x + a1.x + a2.x + a3.x) * inv,
                               (a0.y + a1.y + a2.y + a3.y) * inv,
                               (a0.z + a1.z + a2.z + a3.z) * inv,
                               (a0.w + a1.w + a2.w + a3.w) * inv);
        *(float4*)(g_pooled + g * FH + c) = r;
    }
}

// ================= MLP head =================================================
__global__ void k_head(const float* __restrict__ Wm1, const float* __restrict__ bm1,
                       const float* __restrict__ Wm2, const float* __restrict__ bm2,
                       float* __restrict__ out) {
    __shared__ float sp[FH];
    __shared__ float sh[FH];
    __shared__ float sl[FOUT];
    __shared__ float s_m, s_lse;
    int g = blockIdx.x, t = threadIdx.x;
    sp[t] = g_pooled[g * FH + t];
    __syncthreads();
    float acc = bm1[t];
    #pragma unroll 8
    for (int k = 0; k < FH; k++) acc += sp[k] * Wm1[k * FH + t];
    sh[t] = acc > 0.f ? acc : 0.f;
    __syncthreads();
    if (t < FOUT) {
        float a = bm2[t];
        for (int k = 0; k < FH; k++) a += sh[k] * Wm2[k * FOUT + t];
        sl[t] = a;
    }
    __syncthreads();
    if (t == 0) {
        float m = sl[0];
        for (int o = 1; o < FOUT; o++) m = fmaxf(m, sl[o]);
        float s = 0.f;
        for (int o = 0; o < FOUT; o++) s += expf(sl[o] - m);
        s_m = m; s_lse = logf(s);
    }
    __syncthreads();
    if (t < FOUT) {
        float v = sl[t];
        out[g * FOUT + t]                     = v - s_m - s_lse;
        out[NGRAPH * FOUT + g * FOUT + t]     = 1.0f / (1.0f + expf(-v));
        out[2 * NGRAPH * FOUT + g * FOUT + t] = v;
    }
}

// ================= launch ===================================================
extern "C" void kernel_launch(void* const* d_in, const int* in_sizes, int n_in,
                              void* d_out, int out_size) {
    const float* x     = (const float*)d_in[0];
    const void*  ei    = d_in[1];
    const void*  batch = d_in[3];
    const float* W0  = (const float*)d_in[4];
    const float* W1  = (const float*)d_in[5];
    const float* W2  = (const float*)d_in[6];
    const float* Wm1 = (const float*)d_in[7];
    const float* bm1 = (const float*)d_in[8];
    const float* Wm2 = (const float*)d_in[9];
    const float* bm2 = (const float*)d_in[10];
    float* out = (float*)d_out;

    cudaFuncSetAttribute(k_mma, cudaFuncAttributeMaxDynamicSharedMemorySize, SMEM_TOTAL);

    // ---- graph structure + weight conversion
    k_detect<<<1, 256>>>((const int*)ei);
    k_zero<<<(NODES + 255) / 256, 256>>>();
    k_hist<<<(EDGES + 255) / 256, 256>>>(ei, batch);
    k_scan<<<1, 1024>>>();
    k_scatter<<<(EDGES + 255) / 256, 256>>>(ei);
    k_convAll<<<(256 * FIN + 2 * 256 * FH + 255) / 256, 256>>>(W0, W1, W2);

    dim3 mg((NODES + 127) / 128, 2);

    // ---- layer 0
    k_agg_x<<<(NODES + 7) / 8, 256>>>(x);
    k_mma<<<mg, 256, SMEM_TOTAL>>>(FIN, 0);
    // ---- layer 1
    k_agg_h<<<(NODES + 3) / 4, 256>>>();
    k_mma<<<mg, 256, SMEM_TOTAL>>>(FH, 1);
    // ---- layer 2
    k_agg_h<<<(NODES + 3) / 4, 256>>>();
    k_mma<<<mg, 256, SMEM_TOTAL>>>(FH, 2);

    // ---- pool + head
    k_pool<<<NGRAPH, 256>>>();
    k_head<<<NGRAPH, FH>>>(Wm1, bm1, Wm2, bm2, out);
}

// round 9
// speedup vs baseline: 2.0709x; 1.0307x over previous
#include <cuda_runtime.h>
#include <cuda_bf16.h>
#include <math.h>
#include <stdint.h>

#define NODES 50000
#define EDGES 800000
#define FIN   128
#define FH    256
#define FOUT  10
#define NGRAPH 128
#define SCAN_BLOCKS 49   // ceil(50000/1024)

__device__ __forceinline__ uint32_t smem_u32(const void* p) {
    uint32_t a;
    asm("{ .reg .u64 t; cvta.to.shared.u64 t, %1; cvt.u32.u64 %0, t; }" : "=r"(a) : "l"(p));
    return a;
}
__device__ __forceinline__ uint32_t sw128(uint32_t off) { return off ^ ((off >> 3) & 0x70); }

struct EdgeRec { int src; float norm; };

// ================= scratch ==================================================
__device__ float          g_bufA[(size_t)NODES * FH];
__device__ __nv_bfloat16  g_Ahi[(size_t)NODES * FH];
__device__ __nv_bfloat16  g_Alo[(size_t)NODES * FH];
__device__ __nv_bfloat16  g_Whi0[FH * FIN];
__device__ __nv_bfloat16  g_Wlo0[FH * FIN];
__device__ __nv_bfloat16  g_Whi1[FH * FH];
__device__ __nv_bfloat16  g_Wlo1[FH * FH];
__device__ __nv_bfloat16  g_Whi2[FH * FH];
__device__ __nv_bfloat16  g_Wlo2[FH * FH];
__device__ float   g_dinv[NODES];
__device__ int     g_deg[NODES];
__device__ int     g_rowptr[NODES + 1];
__device__ int     g_cursor[NODES];
__device__ int     g_bsum[SCAN_BLOCKS];
__device__ int     g_boff[SCAN_BLOCKS];
__device__ EdgeRec g_edge[EDGES];
__device__ int     g_gcount[NGRAPH];
__device__ int     g_gstart[NGRAPH + 1];
__device__ int     g_is64;

__device__ __forceinline__ int load_idx(const void* p, size_t i) {
    return g_is64 ? (int)((const long long*)p)[i] : ((const int*)p)[i];
}

// ================= zero + dtype probe (fused) ===============================
__global__ void k_zero(const int* __restrict__ ei32) {
    int i = blockIdx.x * blockDim.x + threadIdx.x;
    if (blockIdx.x == 0) {
        // block 0 additionally probes the index dtype
        __shared__ int nonzero;
        if (threadIdx.x == 0) nonzero = 0;
        __syncthreads();
        int stride = (2 * EDGES) / 256;
        int pos = threadIdx.x * stride + 1;
        if (ei32[pos | 1] != 0) atomicOr(&nonzero, 1);
        __syncthreads();
        if (threadIdx.x == 0) g_is64 = nonzero ? 0 : 1;
    }
    if (i < NODES) { g_deg[i] = 0; g_cursor[i] = 0; }
    if (i < NGRAPH) g_gcount[i] = 0;
}

// ================= histograms ===============================================
__global__ void k_hist(const void* __restrict__ ei, const void* __restrict__ batch) {
    int i = blockIdx.x * blockDim.x + threadIdx.x;
    if (i < EDGES) atomicAdd(&g_deg[load_idx(ei, (size_t)EDGES + i)], 1);
    if (i < NODES) atomicAdd(&g_gcount[load_idx(batch, i)], 1);
}

// ================= parallel 3-phase scan ====================================
// phase 1: per-block exclusive scan of deg -> rowptr (local), dinv, block sums
__global__ void __launch_bounds__(1024) k_scan1() {
    __shared__ int wsum[32];
    int t = threadIdx.x, lane = t & 31, w = t >> 5;
    int i = blockIdx.x * 1024 + t;
    int v = 0;
    if (i < NODES) {
        v = g_deg[i];
        g_dinv[i] = rsqrtf((float)v + 1.0f);
    }
    int x = v;
    #pragma unroll
    for (int off = 1; off < 32; off <<= 1) {
        int y = __shfl_up_sync(0xFFFFFFFFu, x, off);
        if (lane >= off) x += y;
    }
    if (lane == 31) wsum[w] = x;
    __syncthreads();
    if (w == 0) {
        int s = wsum[lane];
        #pragma unroll
        for (int off = 1; off < 32; off <<= 1) {
            int y = __shfl_up_sync(0xFFFFFFFFu, s, off);
            if (lane >= off) s += y;
        }
        wsum[lane] = s;
    }
    __syncthreads();
    int woff = (w > 0) ? wsum[w - 1] : 0;
    if (i < NODES) g_rowptr[i] = woff + x - v;           // block-local exclusive
    if (t == 1023) g_bsum[blockIdx.x] = wsum[31];
}
// phase 2: scan 49 block sums + scan 128 graph counts (one small block)
__global__ void k_scan2() {
    __shared__ int gs[NGRAPH], gv[NGRAPH];
    int t = threadIdx.x;   // 128 threads
    // block-sum exclusive scan (serial by thread 0 — 49 elements, trivial)
    if (t == 0) {
        int run = 0;
        for (int b = 0; b < SCAN_BLOCKS; b++) { g_boff[b] = run; run += g_bsum[b]; }
        g_rowptr[NODES] = run;
    }
    // graph counts scan
    gv[t] = g_gcount[t]; gs[t] = gv[t];
    __syncthreads();
    for (int off = 1; off < NGRAPH; off <<= 1) {
        int add = (t >= off) ? gs[t - off] : 0;
        __syncthreads();
        gs[t] += add;
        __syncthreads();
    }
    g_gstart[t] = gs[t] - gv[t];
    if (t == NGRAPH - 1) g_gstart[NGRAPH] = gs[t];
}
// phase 3: add block offsets
__global__ void __launch_bounds__(1024) k_scan3() {
    int i = blockIdx.x * 1024 + threadIdx.x;
    if (i < NODES) g_rowptr[i] += g_boff[blockIdx.x];
}

__global__ void k_scatter(const void* __restrict__ ei) {
    int e = blockIdx.x * blockDim.x + threadIdx.x;
    if (e >= EDGES) return;
    int row = load_idx(ei, e);
    int col = load_idx(ei, (size_t)EDGES + e);
    int pos = atomicAdd(&g_cursor[col], 1);
    EdgeRec r; r.src = row; r.norm = g_dinv[row] * g_dinv[col];
    g_edge[g_rowptr[col] + pos] = r;
}

// ================= all-weights conversion (upfront, one launch) =============
__global__ void k_convAll(const float* __restrict__ W0, const float* __restrict__ W1,
                          const float* __restrict__ W2) {
    int idx = blockIdx.x * blockDim.x + threadIdx.x;
    float w;
    __nv_bfloat16 *hi, *lo;
    if (idx < 256 * FIN) {
        int n = idx / FIN, k = idx - n * FIN;
        w = W0[(size_t)k * FH + n]; hi = g_Whi0 + idx; lo = g_Wlo0 + idx;
    } else if (idx < 256 * FIN + 256 * FH) {
        int j = idx - 256 * FIN;
        int n = j / FH, k = j - n * FH;
        w = W1[(size_t)k * FH + n]; hi = g_Whi1 + j; lo = g_Wlo1 + j;
    } else if (idx < 256 * FIN + 2 * 256 * FH) {
        int j = idx - 256 * FIN - 256 * FH;
        int n = j / FH, k = j - n * FH;
        w = W2[(size_t)k * FH + n]; hi = g_Whi2 + j; lo = g_Wlo2 + j;
    } else return;
    __nv_bfloat16 h = __float2bfloat16(w);
    *hi = h;
    *lo = __float2bfloat16(w - __bfloat162float(h));
}

// ================= aggregation (float4, unroll 4, bf16 hi/lo out) ===========
__device__ __forceinline__ void split_store4(float4 v, size_t idx) {
    __nv_bfloat16 h0 = __float2bfloat16(v.x), h1 = __float2bfloat16(v.y);
    __nv_bfloat16 h2 = __float2bfloat16(v.z), h3 = __float2bfloat16(v.w);
    __nv_bfloat162* hp = (__nv_bfloat162*)(g_Ahi + idx);
    hp[0] = __nv_bfloat162{h0, h1}; hp[1] = __nv_bfloat162{h2, h3};
    __nv_bfloat16 l0 = __float2bfloat16(v.x - __bfloat162float(h0));
    __nv_bfloat16 l1 = __float2bfloat16(v.y - __bfloat162float(h1));
    __nv_bfloat16 l2 = __float2bfloat16(v.z - __bfloat162float(h2));
    __nv_bfloat16 l3 = __float2bfloat16(v.w - __bfloat162float(h3));
    __nv_bfloat162* lp = (__nv_bfloat162*)(g_Alo + idx);
    lp[0] = __nv_bfloat162{l0, l1}; lp[1] = __nv_bfloat162{l2, l3};
}
template <int D>
__device__ __forceinline__ void agg_body(const float* __restrict__ h, int node, int c) {
    int s = g_rowptr[node], e = g_rowptr[node + 1];
    float di = g_dinv[node];
    float4 self = *(const float4*)(h + (size_t)node * D + c);
    float4 acc = make_float4(di * di * self.x, di * di * self.y,
                             di * di * self.z, di * di * self.w);
    float4 acc2 = make_float4(0.f, 0.f, 0.f, 0.f);
    int j = s;
    for (; j + 3 < e; j += 4) {
        EdgeRec e0 = g_edge[j], e1 = g_edge[j + 1], e2 = g_edge[j + 2], e3 = g_edge[j + 3];
        float4 v0 = *(const float4*)(h + (size_t)e0.src * D + c);
        float4 v1 = *(const float4*)(h + (size_t)e1.src * D + c);
        float4 v2 = *(const float4*)(h + (size_t)e2.src * D + c);
        float4 v3 = *(const float4*)(h + (size_t)e3.src * D + c);
        acc.x  += e0.norm * v0.x + e1.norm * v1.x;
        acc.y  += e0.norm * v0.y + e1.norm * v1.y;
        acc.z  += e0.norm * v0.z + e1.norm * v1.z;
        acc.w  += e0.norm * v0.w + e1.norm * v1.w;
        acc2.x += e2.norm * v2.x + e3.norm * v3.x;
        acc2.y += e2.norm * v2.y + e3.norm * v3.y;
        acc2.z += e2.norm * v2.z + e3.norm * v3.z;
        acc2.w += e2.norm * v2.w + e3.norm * v3.w;
    }
    for (; j < e; j++) {
        EdgeRec e0 = g_edge[j];
        float4 v0 = *(const float4*)(h + (size_t)e0.src * D + c);
        acc.x += e0.norm * v0.x; acc.y += e0.norm * v0.y;
        acc.z += e0.norm * v0.z; acc.w += e0.norm * v0.w;
    }
    acc.x += acc2.x; acc.y += acc2.y; acc.z += acc2.z; acc.w += acc2.w;
    split_store4(acc, (size_t)node * D + c);
}
__global__ void __launch_bounds__(256) k_agg_x(const float* __restrict__ h) {
    int node = blockIdx.x * 8 + (threadIdx.x >> 5);
    if (node >= NODES) return;
    agg_body<FIN>(h, node, (threadIdx.x & 31) * 4);
}
__global__ void __launch_bounds__(256) k_agg_h() {
    int node = blockIdx.x * 4 + (threadIdx.x >> 6);
    if (node >= NODES) return;
    agg_body<FH>(g_bufA, node, (threadIdx.x & 63) * 4);
}

// ================= HMMA GEMM (3-stage pipeline) =============================
#define SMEM_TOTAL 98304
__global__ void __launch_bounds__(256, 2) k_mma(int K, int layer) {
    extern __shared__ char smem[];
    uint32_t sb = smem_u32(smem);
    int tid = threadIdx.x, lane = tid & 31, wid = tid >> 5;
    int wm = wid >> 2, wn = wid & 3;
    int m0 = blockIdx.x * 128, bn = blockIdx.y * 128;
    int cpp = K >> 6, nch = 3 * cpp;
    const __nv_bfloat16* Whi = (layer == 0) ? g_Whi0 : (layer == 1) ? g_Whi1 : g_Whi2;
    const __nv_bfloat16* Wlo = (layer == 0) ? g_Wlo0 : (layer == 1) ? g_Wlo1 : g_Wlo2;

    float acc[4][4][4];
    #pragma unroll
    for (int i = 0; i < 4; i++)
        #pragma unroll
        for (int j = 0; j < 4; j++)
            #pragma unroll
            for (int q = 0; q < 4; q++) acc[i][j][q] = 0.f;

    auto issue = [&](int c) {
        int pass = c / cpp;
        int k0 = (c - pass * cpp) << 6;
        const __nv_bfloat16* As = (pass < 2) ? g_Ahi : g_Alo;
        const __nv_bfloat16* Bs = (pass == 1) ? Wlo : Whi;
        uint32_t ao = (uint32_t)(c % 3) * 32768u;
        uint32_t bo = ao + 16384u;
        #pragma unroll
        for (int i = 0; i < 4; i++) {
            int idx = tid + i * 256;
            int r = idx >> 3, v = idx & 7;
            int gr = m0 + r;
            int ok = gr < NODES;
            const __nv_bfloat16* src = As + (size_t)(ok ? gr : 0) * K + k0 + v * 8;
            uint32_t dst = sb + ao + sw128((uint32_t)(r * 128 + v * 16));
            unsigned long long gs = (unsigned long long)__cvta_generic_to_global((void*)src);
            int sz = ok ? 16 : 0;
            asm volatile("cp.async.cg.shared.global [%0], [%1], 16, %2;" :: "r"(dst), "l"(gs), "r"(sz));
        }
        #pragma unroll
        for (int i = 0; i < 4; i++) {
            int idx = tid + i * 256;
            int r = idx >> 3, v = idx & 7;
            const __nv_bfloat16* src = Bs + (size_t)(bn + r) * K + k0 + v * 8;
            uint32_t dst = sb + bo + sw128((uint32_t)(r * 128 + v * 16));
            unsigned long long gs = (unsigned long long)__cvta_generic_to_global((void*)src);
            asm volatile("cp.async.cg.shared.global [%0], [%1], 16;" :: "r"(dst), "l"(gs));
        }
        asm volatile("cp.async.commit_group;" ::: "memory");
    };

    issue(0);
    issue(1);

    int grp = lane >> 3;
    int rr = (lane & 7) + ((grp & 1) << 3);
    int kof = (grp >= 2) ? 16 : 0;

    for (int c = 0; c < nch; c++) {
        if (c + 2 < nch) { issue(c + 2); asm volatile("cp.async.wait_group 2;" ::: "memory"); }
        else if (c + 1 < nch) { asm volatile("cp.async.wait_group 1;" ::: "memory"); }
        else { asm volatile("cp.async.wait_group 0;" ::: "memory"); }
        __syncthreads();
        uint32_t ab = sb + (uint32_t)(c % 3) * 32768u;
        uint32_t bb = ab + 16384u;
        #pragma unroll
        for (int kk = 0; kk < 4; kk++) {
            uint32_t a[4][4], bf[2][4];
            #pragma unroll
            for (int mt = 0; mt < 4; mt++) {
                uint32_t addr = ab + sw128((uint32_t)((wm * 64 + mt * 16 + rr) * 128 + kk * 32 + kof));
                asm volatile("ldmatrix.sync.aligned.m8n8.x4.shared.b16 {%0,%1,%2,%3}, [%4];"
                    : "=r"(a[mt][0]), "=r"(a[mt][1]), "=r"(a[mt][2]), "=r"(a[mt][3]) : "r"(addr));
            }
            #pragma unroll
            for (int p = 0; p < 2; p++) {
                uint32_t addr = bb + sw128((uint32_t)((wn * 32 + p * 16 + rr) * 128 + kk * 32 + kof));
                asm volatile("ldmatrix.sync.aligned.m8n8.x4.shared.b16 {%0,%1,%2,%3}, [%4];"
                    : "=r"(bf[p][0]), "=r"(bf[p][1]), "=r"(bf[p][2]), "=r"(bf[p][3]) : "r"(addr));
            }
            #pragma unroll
            for (int mt = 0; mt < 4; mt++)
                #pragma unroll
                for (int nt = 0; nt < 4; nt++) {
                    uint32_t b0 = bf[nt >> 1][nt & 1];
                    uint32_t b1 = bf[nt >> 1][(nt & 1) + 2];
                    asm volatile("mma.sync.aligned.m16n8k16.row.col.f32.bf16.bf16.f32 "
                        "{%0,%1,%2,%3}, {%4,%5,%6,%7}, {%8,%9}, {%0,%1,%2,%3};"
                        : "+f"(acc[mt][nt][0]), "+f"(acc[mt][nt][1]),
                          "+f"(acc[mt][nt][2]), "+f"(acc[mt][nt][3])
                        : "r"(a[mt][0]), "r"(a[mt][1]), "r"(a[mt][2]), "r"(a[mt][3]),
                          "r"(b0), "r"(b1));
                }
        }
        __syncthreads();
    }

    int colb = bn + wn * 32 + 2 * (lane & 3);
    #pragma unroll
    for (int mt = 0; mt < 4; mt++) {
        int row = m0 + wm * 64 + mt * 16 + (lane >> 2);
        #pragma unroll
        for (int nt = 0; nt < 4; nt++) {
            if (row < NODES) {
                float2 v = make_float2(fmaxf(acc[mt][nt][0], 0.f), fmaxf(acc[mt][nt][1], 0.f));
                *(float2*)(g_bufA + (size_t)row * FH + colb + nt * 8) = v;
            }
            if (row + 8 < NODES) {
                float2 v = make_float2(fmaxf(acc[mt][nt][2], 0.f), fmaxf(acc[mt][nt][3], 0.f));
                *(float2*)(g_bufA + (size_t)(row + 8) * FH + colb + nt * 8) = v;
            }
        }
    }
}

// ================= fused pool + MLP head ====================================
// block g: mean-pool graph g (256 threads = 64 col-float4 x 4 row groups),
// then the MLP head on the pooled vector, all via shared memory.
__global__ void __launch_bounds__(256) k_poolhead(
        const float* __restrict__ Wm1, const float* __restrict__ bm1,
        const float* __restrict__ Wm2, const float* __restrict__ bm2,
        float* __restrict__ out) {
    __shared__ float4 red[4][64];
    __shared__ float sp[FH];
    __shared__ float sh[FH];
    __shared__ float sl[FOUT];
    __shared__ float s_m, s_lse;
    int g = blockIdx.x;
    int t = threadIdx.x, cg = t & 63, rg = t >> 6;
    int s = g_gstart[g], e = g_gstart[g + 1];
    {
        int c = cg * 4;
        float4 acc = make_float4(0.f, 0.f, 0.f, 0.f);
        for (int i = s + rg; i < e; i += 4) {
            float4 v = *(const float4*)(g_bufA + (size_t)i * FH + c);
            acc.x += v.x; acc.y += v.y; acc.z += v.z; acc.w += v.w;
        }
        red[rg][cg] = acc;
    }
    __syncthreads();
    if (rg == 0) {
        float4 a0 = red[0][cg], a1 = red[1][cg], a2 = red[2][cg], a3 = red[3][cg];
        int cnt = e - s;
        float inv = 1.0f / (float)(cnt > 0 ? cnt : 1);
        int c = cg * 4;
        sp[c]     = (a0.x + a1.x + a2.x + a3.x) * inv;
        sp[c + 1] = (a0.y + a1.y + a2.y + a3.y) * inv;
        sp[c + 2] = (a0.z + a1.z + a2.z + a3.z) * inv;
        sp[c + 3] = (a0.w + a1.w + a2.w + a3.w) * inv;
    }
    __syncthreads();
    float acc = bm1[t];
    #pragma unroll 8
    for (int k = 0; k < FH; k++) acc += sp[k] * Wm1[k * FH + t];
    sh[t] = acc > 0.f ? acc : 0.f;
    __syncthreads();
    if (t < FOUT) {
        float a = bm2[t];
        for (int k = 0; k < FH; k++) a += sh[k] * Wm2[k * FOUT + t];
        sl[t] = a;
    }
    __syncthreads();
    if (t == 0) {
        float m = sl[0];
        for (int o = 1; o < FOUT; o++) m = fmaxf(m, sl[o]);
        float sum = 0.f;
        for (int o = 0; o < FOUT; o++) sum += expf(sl[o] - m);
        s_m = m; s_lse = logf(sum);
    }
    __syncthreads();
    if (t < FOUT) {
        float v = sl[t];
        out[g * FOUT + t]                     = v - s_m - s_lse;
        out[NGRAPH * FOUT + g * FOUT + t]     = 1.0f / (1.0f + expf(-v));
        out[2 * NGRAPH * FOUT + g * FOUT + t] = v;
    }
}

// ================= launch ===================================================
extern "C" void kernel_launch(void* const* d_in, const int* in_sizes, int n_in,
                              void* d_out, int out_size) {
    const float* x     = (const float*)d_in[0];
    const void*  ei    = d_in[1];
    const void*  batch = d_in[3];
    const float* W0  = (const float*)d_in[4];
    const float* W1  = (const float*)d_in[5];
    const float* W2  = (const float*)d_in[6];
    const float* Wm1 = (const float*)d_in[7];
    const float* bm1 = (const float*)d_in[8];
    const float* Wm2 = (const float*)d_in[9];
    const float* bm2 = (const float*)d_in[10];
    float* out = (float*)d_out;

    cudaFuncSetAttribute(k_mma, cudaFuncAttributeMaxDynamicSharedMemorySize, SMEM_TOTAL);

    // ---- graph structure + weight conversion
    k_zero<<<(NODES + 255) / 256, 256>>>((const int*)ei);
    k_hist<<<(EDGES + 255) / 256, 256>>>(ei, batch);
    k_scan1<<<SCAN_BLOCKS, 1024>>>();
    k_scan2<<<1, NGRAPH>>>();
    k_scan3<<<SCAN_BLOCKS, 1024>>>();
    k_scatter<<<(EDGES + 255) / 256, 256>>>(ei);
    k_convAll<<<(256 * FIN + 2 * 256 * FH + 255) / 256, 256>>>(W0, W1, W2);

    dim3 mg((NODES + 127) / 128, 2);

    // ---- layer 0
    k_agg_x<<<(NODES + 7) / 8, 256>>>(x);
    k_mma<<<mg, 256, SMEM_TOTAL>>>(FIN, 0);
    // ---- layer 1
    k_agg_h<<<(NODES + 3) / 4, 256>>>();
    k_mma<<<mg, 256, SMEM_TOTAL>>>(FH, 1);
    // ---- layer 2
    k_agg_h<<<(NODES + 3) / 4, 256>>>();
    k_mma<<<mg, 256, SMEM_TOTAL>>>(FH, 2);

    // ---- fused pool + head
    k_poolhead<<<NGRAPH, 256>>>(Wm1, bm1, Wm2, bm2, out);
}

// round 11
// speedup vs baseline: 2.5069x; 1.2105x over previous
#include <cuda_runtime.h>
#include <cuda_bf16.h>
#include <math.h>
#include <stdint.h>

#define NODES 50000
#define EDGES 800000
#define FIN   128
#define FH    256
#define FOUT  10
#define NGRAPH 128
#define SCAN_BLOCKS 49   // ceil(50000/1024)

__device__ __forceinline__ uint32_t smem_u32(const void* p) {
    uint32_t a;
    asm("{ .reg .u64 t; cvta.to.shared.u64 t, %1; cvt.u32.u64 %0, t; }" : "=r"(a) : "l"(p));
    return a;
}
__device__ __forceinline__ uint32_t sw128(uint32_t off) { return off ^ ((off >> 3) & 0x70); }
__device__ __forceinline__ float bf_lo(uint32_t u) { return __uint_as_float(u << 16); }
__device__ __forceinline__ float bf_hi(uint32_t u) { return __uint_as_float(u & 0xFFFF0000u); }

struct EdgeRec { int src; float norm; };

// ================= scratch ==================================================
__device__ float          g_bufA[(size_t)NODES * FH];   // layer2 output (fp32, pooled)
__device__ __nv_bfloat16  g_hbf[(size_t)NODES * FH];    // layer0/1 output (bf16, gathered)
__device__ __nv_bfloat16  g_xbf[(size_t)NODES * FIN];   // x in bf16 (gathered)
__device__ __nv_bfloat16  g_Ahi[(size_t)NODES * FH];
__device__ __nv_bfloat16  g_Alo[(size_t)NODES * FH];
__device__ __nv_bfloat16  g_Whi0[FH * FIN];
__device__ __nv_bfloat16  g_Wlo0[FH * FIN];
__device__ __nv_bfloat16  g_Whi1[FH * FH];
__device__ __nv_bfloat16  g_Wlo1[FH * FH];
__device__ __nv_bfloat16  g_Whi2[FH * FH];
__device__ __nv_bfloat16  g_Wlo2[FH * FH];
__device__ float   g_dinv[NODES];
__device__ int     g_deg[NODES];
__device__ int     g_rowptr[NODES + 1];
__device__ int     g_cursor[NODES];
__device__ int     g_bsum[SCAN_BLOCKS];
__device__ int     g_boff[SCAN_BLOCKS];
__device__ EdgeRec g_edge[EDGES];
__device__ int     g_gcount[NGRAPH];
__device__ int     g_gstart[NGRAPH + 1];
__device__ int     g_is64;

__device__ __forceinline__ int load_idx(const void* p, size_t i) {
    return g_is64 ? (int)((const long long*)p)[i] : ((const int*)p)[i];
}

// ================= zero + dtype probe (fused) ===============================
__global__ void k_zero(const int* __restrict__ ei32) {
    int i = blockIdx.x * blockDim.x + threadIdx.x;
    if (blockIdx.x == 0) {
        __shared__ int nonzero;
        if (threadIdx.x == 0) nonzero = 0;
        __syncthreads();
        int stride = (2 * EDGES) / 256;
        int pos = threadIdx.x * stride + 1;
        if (ei32[pos | 1] != 0) atomicOr(&nonzero, 1);
        __syncthreads();
        if (threadIdx.x == 0) g_is64 = nonzero ? 0 : 1;
    }
    if (i < NODES) { g_deg[i] = 0; g_cursor[i] = 0; }
    if (i < NGRAPH) g_gcount[i] = 0;
}

// ================= histograms ===============================================
__global__ void k_hist(const void* __restrict__ ei, const void* __restrict__ batch) {
    int i = blockIdx.x * blockDim.x + threadIdx.x;
    if (i < EDGES) atomicAdd(&g_deg[load_idx(ei, (size_t)EDGES + i)], 1);
    if (i < NODES) atomicAdd(&g_gcount[load_idx(batch, i)], 1);
}

// ================= parallel 3-phase scan ====================================
__global__ void __launch_bounds__(1024) k_scan1() {
    __shared__ int wsum[32];
    int t = threadIdx.x, lane = t & 31, w = t >> 5;
    int i = blockIdx.x * 1024 + t;
    int v = 0;
    if (i < NODES) {
        v = g_deg[i];
        g_dinv[i] = rsqrtf((float)v + 1.0f);
    }
    int x = v;
    #pragma unroll
    for (int off = 1; off < 32; off <<= 1) {
        int y = __shfl_up_sync(0xFFFFFFFFu, x, off);
        if (lane >= off) x += y;
    }
    if (lane == 31) wsum[w] = x;
    __syncthreads();
    if (w == 0) {
        int s = wsum[lane];
        #pragma unroll
        for (int off = 1; off < 32; off <<= 1) {
            int y = __shfl_up_sync(0xFFFFFFFFu, s, off);
            if (lane >= off) s += y;
        }
        wsum[lane] = s;
    }
    __syncthreads();
    int woff = (w > 0) ? wsum[w - 1] : 0;
    if (i < NODES) g_rowptr[i] = woff + x - v;
    if (t == 1023) g_bsum[blockIdx.x] = wsum[31];
}
__global__ void k_scan2() {
    __shared__ int gs[NGRAPH], gv[NGRAPH];
    int t = threadIdx.x;   // 128
    if (t == 0) {
        int run = 0;
        for (int b = 0; b < SCAN_BLOCKS; b++) { g_boff[b] = run; run += g_bsum[b]; }
        g_rowptr[NODES] = run;
    }
    gv[t] = g_gcount[t]; gs[t] = gv[t];
    __syncthreads();
    for (int off = 1; off < NGRAPH; off <<= 1) {
        int add = (t >= off) ? gs[t - off] : 0;
        __syncthreads();
        gs[t] += add;
        __syncthreads();
    }
    g_gstart[t] = gs[t] - gv[t];
    if (t == NGRAPH - 1) g_gstart[NGRAPH] = gs[t];
}
__global__ void __launch_bounds__(1024) k_scan3() {
    int i = blockIdx.x * 1024 + threadIdx.x;
    if (i < NODES) g_rowptr[i] += g_boff[blockIdx.x];
}

__global__ void k_scatter(const void* __restrict__ ei) {
    int e = blockIdx.x * blockDim.x + threadIdx.x;
    if (e >= EDGES) return;
    int row = load_idx(ei, e);
    int col = load_idx(ei, (size_t)EDGES + e);
    int pos = atomicAdd(&g_cursor[col], 1);
    EdgeRec r; r.src = row; r.norm = g_dinv[row] * g_dinv[col];
    g_edge[g_rowptr[col] + pos] = r;
}

// ================= weight + x conversion ====================================
__global__ void k_convAll(const float* __restrict__ W0, const float* __restrict__ W1,
                          const float* __restrict__ W2) {
    int idx = blockIdx.x * blockDim.x + threadIdx.x;
    float w;
    __nv_bfloat16 *hi, *lo;
    if (idx < 256 * FIN) {
        int n = idx / FIN, k = idx - n * FIN;
        w = W0[(size_t)k * FH + n]; hi = g_Whi0 + idx; lo = g_Wlo0 + idx;
    } else if (idx < 256 * FIN + 256 * FH) {
        int j = idx - 256 * FIN;
        int n = j / FH, k = j - n * FH;
        w = W1[(size_t)k * FH + n]; hi = g_Whi1 + j; lo = g_Wlo1 + j;
    } else if (idx < 256 * FIN + 2 * 256 * FH) {
        int j = idx - 256 * FIN - 256 * FH;
        int n = j / FH, k = j - n * FH;
        w = W2[(size_t)k * FH + n]; hi = g_Whi2 + j; lo = g_Wlo2 + j;
    } else return;
    __nv_bfloat16 h = __float2bfloat16(w);
    *hi = h;
    *lo = __float2bfloat16(w - __bfloat162float(h));
}
// x [N,128] fp32 -> bf16 (each thread: 4 elements)
__global__ void k_convX(const float* __restrict__ x) {
    int i = blockIdx.x * blockDim.x + threadIdx.x;
    if (i * 4 >= NODES * FIN) return;
    float4 v = ((const float4*)x)[i];
    __nv_bfloat162* dst = (__nv_bfloat162*)(g_xbf + (size_t)i * 4);
    dst[0] = __nv_bfloat162{__float2bfloat16(v.x), __float2bfloat16(v.y)};
    dst[1] = __nv_bfloat162{__float2bfloat16(v.z), __float2bfloat16(v.w)};
}

// ================= aggregation (bf16 gather, 8 cols/thread) =================
template <int D>
__device__ __forceinline__ void agg_body_bf(const __nv_bfloat16* __restrict__ h,
                                            int node, int c) {
    int s = g_rowptr[node], e = g_rowptr[node + 1];
    float di = g_dinv[node];
    float d2 = di * di;
    uint4 sv = *(const uint4*)(h + (size_t)node * D + c);
    float acc[8];
    acc[0] = d2 * bf_lo(sv.x); acc[1] = d2 * bf_hi(sv.x);
    acc[2] = d2 * bf_lo(sv.y); acc[3] = d2 * bf_hi(sv.y);
    acc[4] = d2 * bf_lo(sv.z); acc[5] = d2 * bf_hi(sv.z);
    acc[6] = d2 * bf_lo(sv.w); acc[7] = d2 * bf_hi(sv.w);
    int j = s;
    for (; j + 3 < e; j += 4) {
        EdgeRec e0 = g_edge[j], e1 = g_edge[j + 1], e2 = g_edge[j + 2], e3 = g_edge[j + 3];
        uint4 v0 = *(const uint4*)(h + (size_t)e0.src * D + c);
        uint4 v1 = *(const uint4*)(h + (size_t)e1.src * D + c);
        uint4 v2 = *(const uint4*)(h + (size_t)e2.src * D + c);
        uint4 v3 = *(const uint4*)(h + (size_t)e3.src * D + c);
        acc[0] += e0.norm * bf_lo(v0.x) + e1.norm * bf_lo(v1.x) + e2.norm * bf_lo(v2.x) + e3.norm * bf_lo(v3.x);
        acc[1] += e0.norm * bf_hi(v0.x) + e1.norm * bf_hi(v1.x) + e2.norm * bf_hi(v2.x) + e3.norm * bf_hi(v3.x);
        acc[2] += e0.norm * bf_lo(v0.y) + e1.norm * bf_lo(v1.y) + e2.norm * bf_lo(v2.y) + e3.norm * bf_lo(v3.y);
        acc[3] += e0.norm * bf_hi(v0.y) + e1.norm * bf_hi(v1.y) + e2.norm * bf_hi(v2.y) + e3.norm * bf_hi(v3.y);
        acc[4] += e0.norm * bf_lo(v0.z) + e1.norm * bf_lo(v1.z) + e2.norm * bf_lo(v2.z) + e3.norm * bf_lo(v3.z);
        acc[5] += e0.norm * bf_hi(v0.z) + e1.norm * bf_hi(v1.z) + e2.norm * bf_hi(v2.z) + e3.norm * bf_hi(v3.z);
        acc[6] += e0.norm * bf_lo(v0.w) + e1.norm * bf_lo(v1.w) + e2.norm * bf_lo(v2.w) + e3.norm * bf_lo(v3.w);
        acc[7] += e0.norm * bf_hi(v0.w) + e1.norm * bf_hi(v1.w) + e2.norm * bf_hi(v2.w) + e3.norm * bf_hi(v3.w);
    }
    for (; j < e; j++) {
        EdgeRec e0 = g_edge[j];
        uint4 v0 = *(const uint4*)(h + (size_t)e0.src * D + c);
        acc[0] += e0.norm * bf_lo(v0.x); acc[1] += e0.norm * bf_hi(v0.x);
        acc[2] += e0.norm * bf_lo(v0.y); acc[3] += e0.norm * bf_hi(v0.y);
        acc[4] += e0.norm * bf_lo(v0.z); acc[5] += e0.norm * bf_hi(v0.z);
        acc[6] += e0.norm * bf_lo(v0.w); acc[7] += e0.norm * bf_hi(v0.w);
    }
    // split hi/lo, store 16B each
    size_t base = (size_t)node * D + c;
    __nv_bfloat16 hi8[8], lo8[8];
    #pragma unroll
    for (int q = 0; q < 8; q++) {
        hi8[q] = __float2bfloat16(acc[q]);
        lo8[q] = __float2bfloat16(acc[q] - __bfloat162float(hi8[q]));
    }
    *(uint4*)(g_Ahi + base) = *(uint4*)hi8;
    *(uint4*)(g_Alo + base) = *(uint4*)lo8;
}
// layer 0: gather g_xbf, 16 threads/node (128 cols / 8), 16 nodes/block
__global__ void __launch_bounds__(256) k_agg_x() {
    int node = blockIdx.x * 16 + (threadIdx.x >> 4);
    if (node >= NODES) return;
    agg_body_bf<FIN>(g_xbf, node, (threadIdx.x & 15) * 8);
}
// layers 1,2: gather g_hbf, 32 threads/node, 8 nodes/block
__global__ void __launch_bounds__(256) k_agg_h() {
    int node = blockIdx.x * 8 + (threadIdx.x >> 5);
    if (node >= NODES) return;
    agg_body_bf<FH>(g_hbf, node, (threadIdx.x & 31) * 8);
}

// ================= HMMA GEMM (3-stage pipeline) =============================
#define SMEM_TOTAL 98304
__global__ void __launch_bounds__(256, 2) k_mma(int K, int layer) {
    extern __shared__ char smem[];
    uint32_t sb = smem_u32(smem);
    int tid = threadIdx.x, lane = tid & 31, wid = tid >> 5;
    int wm = wid >> 2, wn = wid & 3;
    int m0 = blockIdx.x * 128, bn = blockIdx.y * 128;
    int cpp = K >> 6, nch = 3 * cpp;
    const __nv_bfloat16* Whi = (layer == 0) ? g_Whi0 : (layer == 1) ? g_Whi1 : g_Whi2;
    const __nv_bfloat16* Wlo = (layer == 0) ? g_Wlo0 : (layer == 1) ? g_Wlo1 : g_Wlo2;

    float acc[4][4][4];
    #pragma unroll
    for (int i = 0; i < 4; i++)
        #pragma unroll
        for (int j = 0; j < 4; j++)
            #pragma unroll
            for (int q = 0; q < 4; q++) acc[i][j][q] = 0.f;

    auto issue = [&](int c) {
        int pass = c / cpp;
        int k0 = (c - pass * cpp) << 6;
        const __nv_bfloat16* As = (pass < 2) ? g_Ahi : g_Alo;
        const __nv_bfloat16* Bs = (pass == 1) ? Wlo : Whi;
        uint32_t ao = (uint32_t)(c % 3) * 32768u;
        uint32_t bo = ao + 16384u;
        #pragma unroll
        for (int i = 0; i < 4; i++) {
            int idx = tid + i * 256;
            int r = idx >> 3, v = idx & 7;
            int gr = m0 + r;
            int ok = gr < NODES;
            const __nv_bfloat16* src = As + (size_t)(ok ? gr : 0) * K + k0 + v * 8;
            uint32_t dst = sb + ao + sw128((uint32_t)(r * 128 + v * 16));
            unsigned long long gs = (unsigned long long)__cvta_generic_to_global((void*)src);
            int sz = ok ? 16 : 0;
            asm volatile("cp.async.cg.shared.global [%0], [%1], 16, %2;" :: "r"(dst), "l"(gs), "r"(sz));
        }
        #pragma unroll
        for (int i = 0; i < 4; i++) {
            int idx = tid + i * 256;
            int r = idx >> 3, v = idx & 7;
            const __nv_bfloat16* src = Bs + (size_t)(bn + r) * K + k0 + v * 8;
            uint32_t dst = sb + bo + sw128((uint32_t)(r * 128 + v * 16));
            unsigned long long gs = (unsigned long long)__cvta_generic_to_global((void*)src);
            asm volatile("cp.async.cg.shared.global [%0], [%1], 16;" :: "r"(dst), "l"(gs));
        }
        asm volatile("cp.async.commit_group;" ::: "memory");
    };

    issue(0);
    issue(1);

    int grp = lane >> 3;
    int rr = (lane & 7) + ((grp & 1) << 3);
    int kof = (grp >= 2) ? 16 : 0;

    for (int c = 0; c < nch; c++) {
        if (c + 2 < nch) { issue(c + 2); asm volatile("cp.async.wait_group 2;" ::: "memory"); }
        else if (c + 1 < nch) { asm volatile("cp.async.wait_group 1;" ::: "memory"); }
        else { asm volatile("cp.async.wait_group 0;" ::: "memory"); }
        __syncthreads();
        uint32_t ab = sb + (uint32_t)(c % 3) * 32768u;
        uint32_t bb = ab + 16384u;
        #pragma unroll
        for (int kk = 0; kk < 4; kk++) {
            uint32_t a[4][4], bf[2][4];
            #pragma unroll
            for (int mt = 0; mt < 4; mt++) {
                uint32_t addr = ab + sw128((uint32_t)((wm * 64 + mt * 16 + rr) * 128 + kk * 32 + kof));
                asm volatile("ldmatrix.sync.aligned.m8n8.x4.shared.b16 {%0,%1,%2,%3}, [%4];"
                    : "=r"(a[mt][0]), "=r"(a[mt][1]), "=r"(a[mt][2]), "=r"(a[mt][3]) : "r"(addr));
            }
            #pragma unroll
            for (int p = 0; p < 2; p++) {
                uint32_t addr = bb + sw128((uint32_t)((wn * 32 + p * 16 + rr) * 128 + kk * 32 + kof));
                asm volatile("ldmatrix.sync.aligned.m8n8.x4.shared.b16 {%0,%1,%2,%3}, [%4];"
                    : "=r"(bf[p][0]), "=r"(bf[p][1]), "=r"(bf[p][2]), "=r"(bf[p][3]) : "r"(addr));
            }
            #pragma unroll
            for (int mt = 0; mt < 4; mt++)
                #pragma unroll
                for (int nt = 0; nt < 4; nt++) {
                    uint32_t b0 = bf[nt >> 1][nt & 1];
                    uint32_t b1 = bf[nt >> 1][(nt & 1) + 2];
                    asm volatile("mma.sync.aligned.m16n8k16.row.col.f32.bf16.bf16.f32 "
                        "{%0,%1,%2,%3}, {%4,%5,%6,%7}, {%8,%9}, {%0,%1,%2,%3};"
                        : "+f"(acc[mt][nt][0]), "+f"(acc[mt][nt][1]),
                          "+f"(acc[mt][nt][2]), "+f"(acc[mt][nt][3])
                        : "r"(a[mt][0]), "r"(a[mt][1]), "r"(a[mt][2]), "r"(a[mt][3]),
                          "r"(b0), "r"(b1));
                }
        }
        __syncthreads();
    }

    // epilogue: relu; layers 0,1 -> bf16 g_hbf, layer 2 -> fp32 g_bufA
    int colb = bn + wn * 32 + 2 * (lane & 3);
    bool bf16out = (layer < 2);
    #pragma unroll
    for (int mt = 0; mt < 4; mt++) {
        int row = m0 + wm * 64 + mt * 16 + (lane >> 2);
        #pragma unroll
        for (int nt = 0; nt < 4; nt++) {
            float v0 = fmaxf(acc[mt][nt][0], 0.f), v1 = fmaxf(acc[mt][nt][1], 0.f);
            float v2 = fmaxf(acc[mt][nt][2], 0.f), v3 = fmaxf(acc[mt][nt][3], 0.f);
            if (bf16out) {
                if (row < NODES)
                    *(__nv_bfloat162*)(g_hbf + (size_t)row * FH + colb + nt * 8) =
                        __nv_bfloat162{__float2bfloat16(v0), __float2bfloat16(v1)};
                if (row + 8 < NODES)
                    *(__nv_bfloat162*)(g_hbf + (size_t)(row + 8) * FH + colb + nt * 8) =
                        __nv_bfloat162{__float2bfloat16(v2), __float2bfloat16(v3)};
            } else {
                if (row < NODES)
                    *(float2*)(g_bufA + (size_t)row * FH + colb + nt * 8) = make_float2(v0, v1);
                if (row + 8 < NODES)
                    *(float2*)(g_bufA + (size_t)(row + 8) * FH + colb + nt * 8) = make_float2(v2, v3);
            }
        }
    }
}

// ================= fused pool + MLP head ====================================
__global__ void __launch_bounds__(256) k_poolhead(
        const float* __restrict__ Wm1, const float* __restrict__ bm1,
        const float* __restrict__ Wm2, const float* __restrict__ bm2,
        float* __restrict__ out) {
    __shared__ float4 red[4][64];
    __shared__ float sp[FH];
    __shared__ float sh[FH];
    __shared__ float sl[FOUT];
    __shared__ float s_m, s_lse;
    int g = blockIdx.x;
    int t = threadIdx.x, cg = t & 63, rg = t >> 6;
    int s = g_gstart[g], e = g_gstart[g + 1];
    {
        int c = cg * 4;
        float4 acc = make_float4(0.f, 0.f, 0.f, 0.f);
        for (int i = s + rg; i < e; i += 4) {
            float4 v = *(const float4*)(g_bufA + (size_t)i * FH + c);
            acc.x += v.x; acc.y += v.y; acc.z += v.z; acc.w += v.w;
        }
        red[rg][cg] = acc;
    }
    __syncthreads();
    if (rg == 0) {
        float4 a0 = red[0][cg], a1 = red[1][cg], a2 = red[2][cg], a3 = red[3][cg];
        int cnt = e - s;
        float inv = 1.0f / (float)(cnt > 0 ? cnt : 1);
        int c = cg * 4;
        sp[c]     = (a0.x + a1.x + a2.x + a3.x) * inv;
        sp[c + 1] = (a0.y + a1.y + a2.y + a3.y) * inv;
        sp[c + 2] = (a0.z + a1.z + a2.z + a3.z) * inv;
        sp[c + 3] = (a0.w + a1.w + a2.w + a3.w) * inv;
    }
    __syncthreads();
    float acc = bm1[t];
    #pragma unroll 8
    for (int k = 0; k < FH; k++) acc += sp[k] * Wm1[k * FH + t];
    sh[t] = acc > 0.f ? acc : 0.f;
    __syncthreads();
    if (t < FOUT) {
        float a = bm2[t];
        for (int k = 0; k < FH; k++) a += sh[k] * Wm2[k * FOUT + t];
        sl[t] = a;
    }
    __syncthreads();
    if (t == 0) {
        float m = sl[0];
        for (int o = 1; o < FOUT; o++) m = fmaxf(m, sl[o]);
        float sum = 0.f;
        for (int o = 0; o < FOUT; o++) sum += expf(sl[o] - m);
        s_m = m; s_lse = logf(sum);
    }
    __syncthreads();
    if (t < FOUT) {
        float v = sl[t];
        out[g * FOUT + t]                     = v - s_m - s_lse;
        out[NGRAPH * FOUT + g * FOUT + t]     = 1.0f / (1.0f + expf(-v));
        out[2 * NGRAPH * FOUT + g * FOUT + t] = v;
    }
}

// ================= launch ===================================================
extern "C" void kernel_launch(void* const* d_in, const int* in_sizes, int n_in,
                              void* d_out, int out_size) {
    const float* x     = (const float*)d_in[0];
    const void*  ei    = d_in[1];
    const void*  batch = d_in[3];
    const float* W0  = (const float*)d_in[4];
    const float* W1  = (const float*)d_in[5];
    const float* W2  = (const float*)d_in[6];
    const float* Wm1 = (const float*)d_in[7];
    const float* bm1 = (const float*)d_in[8];
    const float* Wm2 = (const float*)d_in[9];
    const float* bm2 = (const float*)d_in[10];
    float* out = (float*)d_out;

    cudaFuncSetAttribute(k_mma, cudaFuncAttributeMaxDynamicSharedMemorySize, SMEM_TOTAL);

    // ---- graph structure + conversions
    k_zero<<<(NODES + 255) / 256, 256>>>((const int*)ei);
    k_hist<<<(EDGES + 255) / 256, 256>>>(ei, batch);
    k_scan1<<<SCAN_BLOCKS, 1024>>>();
    k_scan2<<<1, NGRAPH>>>();
    k_scan3<<<SCAN_BLOCKS, 1024>>>();
    k_scatter<<<(EDGES + 255) / 256, 256>>>(ei);
    k_convAll<<<(256 * FIN + 2 * 256 * FH + 255) / 256, 256>>>(W0, W1, W2);
    k_convX<<<(NODES * FIN / 4 + 255) / 256, 256>>>(x);

    dim3 mg((NODES + 127) / 128, 2);

    // ---- layer 0
    k_agg_x<<<(NODES + 15) / 16, 256>>>();
    k_mma<<<mg, 256, SMEM_TOTAL>>>(FIN, 0);
    // ---- layer 1
    k_agg_h<<<(NODES + 7) / 8, 256>>>();
    k_mma<<<mg, 256, SMEM_TOTAL>>>(FH, 1);
    // ---- layer 2
    k_agg_h<<<(NODES + 7) / 8, 256>>>();
    k_mma<<<mg, 256, SMEM_TOTAL>>>(FH, 2);

    // ---- fused pool + head
    k_poolhead<<<NGRAPH, 256>>>(Wm1, bm1, Wm2, bm2, out);
}

// round 12
// speedup vs baseline: 3.6992x; 1.4756x over previous
#include <cuda_runtime.h>
#include <cuda_fp16.h>
#include <math.h>
#include <stdint.h>

#define NODES 50000
#define EDGES 800000
#define FIN   128
#define FH    256
#define FOUT  10
#define NGRAPH 128
#define SCAN_BLOCKS 49   // ceil(50000/1024)

__device__ __forceinline__ uint32_t smem_u32(const void* p) {
    uint32_t a;
    asm("{ .reg .u64 t; cvta.to.shared.u64 t, %1; cvt.u32.u64 %0, t; }" : "=r"(a) : "l"(p));
    return a;
}
__device__ __forceinline__ uint32_t sw128(uint32_t off) { return off ^ ((off >> 3) & 0x70); }
__device__ __forceinline__ float2 h2f(uint32_t u) {
    __half2 h = *reinterpret_cast<__half2*>(&u);
    return __half22float2(h);
}

struct EdgeRec { int src; float norm; };

// ================= scratch ==================================================
__device__ float   g_bufA[(size_t)NODES * FH];   // layer2 output (fp32, pooled)
__device__ __half  g_h[(size_t)NODES * FH];      // layer0/1 output (fp16, gathered)
__device__ __half  g_x16[(size_t)NODES * FIN];   // x in fp16 (gathered)
__device__ __half  g_Ah[(size_t)NODES * FH];     // agg output (GEMM A input)
__device__ __half  g_W0[FH * FIN];               // weights [N=256][K] fp16
__device__ __half  g_W1[FH * FH];
__device__ __half  g_W2[FH * FH];
__device__ float   g_dinv[NODES];
__device__ int     g_deg[NODES];
__device__ int     g_rowptr[NODES + 1];          // block-local prefix (+ g_boff)
__device__ int     g_cursor[NODES];
__device__ int     g_bsum[SCAN_BLOCKS];
__device__ int     g_boff[SCAN_BLOCKS];
__device__ EdgeRec g_edge[EDGES];
__device__ int     g_gcount[NGRAPH];
__device__ int     g_gstart[NGRAPH + 1];
__device__ int     g_is64;

__device__ __forceinline__ int load_idx(const void* p, size_t i) {
    return g_is64 ? (int)((const long long*)p)[i] : ((const int*)p)[i];
}

// ================= zero + dtype probe (fused) ===============================
__global__ void k_zero(const int* __restrict__ ei32) {
    int i = blockIdx.x * blockDim.x + threadIdx.x;
    if (blockIdx.x == 0) {
        __shared__ int nonzero;
        if (threadIdx.x == 0) nonzero = 0;
        __syncthreads();
        int stride = (2 * EDGES) / 256;
        int pos = threadIdx.x * stride + 1;
        if (ei32[pos | 1] != 0) atomicOr(&nonzero, 1);
        __syncthreads();
        if (threadIdx.x == 0) g_is64 = nonzero ? 0 : 1;
    }
    if (i < NODES) { g_deg[i] = 0; g_cursor[i] = 0; }
    if (i < NGRAPH) g_gcount[i] = 0;
}

// ================= histograms ===============================================
__global__ void k_hist(const void* __restrict__ ei, const void* __restrict__ batch) {
    int i = blockIdx.x * blockDim.x + threadIdx.x;
    if (i < EDGES) atomicAdd(&g_deg[load_idx(ei, (size_t)EDGES + i)], 1);
    if (i < NODES) atomicAdd(&g_gcount[load_idx(batch, i)], 1);
}

// ================= parallel scan (block-local; consumers add g_boff) ========
__global__ void __launch_bounds__(1024) k_scan1() {
    __shared__ int wsum[32];
    int t = threadIdx.x, lane = t & 31, w = t >> 5;
    int i = blockIdx.x * 1024 + t;
    int v = 0;
    if (i < NODES) {
        v = g_deg[i];
        g_dinv[i] = rsqrtf((float)v + 1.0f);
    }
    int x = v;
    #pragma unroll
    for (int off = 1; off < 32; off <<= 1) {
        int y = __shfl_up_sync(0xFFFFFFFFu, x, off);
        if (lane >= off) x += y;
    }
    if (lane == 31) wsum[w] = x;
    __syncthreads();
    if (w == 0) {
        int s = wsum[lane];
        #pragma unroll
        for (int off = 1; off < 32; off <<= 1) {
            int y = __shfl_up_sync(0xFFFFFFFFu, s, off);
            if (lane >= off) s += y;
        }
        wsum[lane] = s;
    }
    __syncthreads();
    int woff = (w > 0) ? wsum[w - 1] : 0;
    if (i <= NODES) g_rowptr[i] = woff + x - v;   // includes i == NODES
    if (t == 1023) g_bsum[blockIdx.x] = wsum[31];
}
__global__ void k_scan2() {
    __shared__ int gs[NGRAPH], gv[NGRAPH];
    int t = threadIdx.x;   // 128
    if (t == 0) {
        int run = 0;
        for (int b = 0; b < SCAN_BLOCKS; b++) { g_boff[b] = run; run += g_bsum[b]; }
    }
    gv[t] = g_gcount[t]; gs[t] = gv[t];
    __syncthreads();
    for (int off = 1; off < NGRAPH; off <<= 1) {
        int add = (t >= off) ? gs[t - off] : 0;
        __syncthreads();
        gs[t] += add;
        __syncthreads();
    }
    g_gstart[t] = gs[t] - gv[t];
    if (t == NGRAPH - 1) g_gstart[NGRAPH] = gs[t];
}
__device__ __forceinline__ int rowptr_abs(int i) {
    return g_rowptr[i] + g_boff[i >> 10];
}

__global__ void k_scatter(const void* __restrict__ ei) {
    int e = blockIdx.x * blockDim.x + threadIdx.x;
    if (e >= EDGES) return;
    int row = load_idx(ei, e);
    int col = load_idx(ei, (size_t)EDGES + e);
    int pos = atomicAdd(&g_cursor[col], 1);
    EdgeRec r; r.src = row; r.norm = g_dinv[row] * g_dinv[col];
    g_edge[rowptr_abs(col) + pos] = r;
}

// ================= weights + x conversion (one launch) ======================
#define NWELEM (256 * FIN + 2 * 256 * FH)   // 163840
__global__ void k_conv(const float* __restrict__ x, const float* __restrict__ W0,
                       const float* __restrict__ W1, const float* __restrict__ W2) {
    int i = blockIdx.x * blockDim.x + threadIdx.x;
    // x: 4 floats per thread
    if (i < NODES * FIN / 4) {
        float4 v = ((const float4*)x)[i];
        __half2* dst = (__half2*)(g_x16 + (size_t)i * 4);
        dst[0] = __floats2half2_rn(v.x, v.y);
        dst[1] = __floats2half2_rn(v.z, v.w);
    }
    // weights: 1 element per thread (transposed read)
    if (i < NWELEM) {
        float w; __half* dst;
        if (i < 256 * FIN) {
            int n = i / FIN, k = i - n * FIN;
            w = W0[(size_t)k * FH + n]; dst = g_W0 + i;
        } else if (i < 256 * FIN + 256 * FH) {
            int j = i - 256 * FIN;
            int n = j / FH, k = j - n * FH;
            w = W1[(size_t)k * FH + n]; dst = g_W1 + j;
        } else {
            int j = i - 256 * FIN - 256 * FH;
            int n = j / FH, k = j - n * FH;
            w = W2[(size_t)k * FH + n]; dst = g_W2 + j;
        }
        *dst = __float2half(w);
    }
}

// ================= aggregation (fp16 gather, 8 cols/thread) =================
template <int D>
__device__ __forceinline__ void agg_body16(const __half* __restrict__ h, int node, int c) {
    int s = rowptr_abs(node), e = rowptr_abs(node + 1);
    float di = g_dinv[node];
    float d2 = di * di;
    uint4 sv = *(const uint4*)(h + (size_t)node * D + c);
    float2 p0 = h2f(sv.x), p1 = h2f(sv.y), p2 = h2f(sv.z), p3 = h2f(sv.w);
    float acc[8] = { d2 * p0.x, d2 * p0.y, d2 * p1.x, d2 * p1.y,
                     d2 * p2.x, d2 * p2.y, d2 * p3.x, d2 * p3.y };
    int j = s;
    for (; j + 3 < e; j += 4) {
        EdgeRec e0 = g_edge[j], e1 = g_edge[j + 1], e2 = g_edge[j + 2], e3 = g_edge[j + 3];
        uint4 v0 = *(const uint4*)(h + (size_t)e0.src * D + c);
        uint4 v1 = *(const uint4*)(h + (size_t)e1.src * D + c);
        uint4 v2 = *(const uint4*)(h + (size_t)e2.src * D + c);
        uint4 v3 = *(const uint4*)(h + (size_t)e3.src * D + c);
        float2 a0, a1, a2, a3;
        a0 = h2f(v0.x); a1 = h2f(v1.x); a2 = h2f(v2.x); a3 = h2f(v3.x);
        acc[0] += e0.norm * a0.x + e1.norm * a1.x + e2.norm * a2.x + e3.norm * a3.x;
        acc[1] += e0.norm * a0.y + e1.norm * a1.y + e2.norm * a2.y + e3.norm * a3.y;
        a0 = h2f(v0.y); a1 = h2f(v1.y); a2 = h2f(v2.y); a3 = h2f(v3.y);
        acc[2] += e0.norm * a0.x + e1.norm * a1.x + e2.norm * a2.x + e3.norm * a3.x;
        acc[3] += e0.norm * a0.y + e1.norm * a1.y + e2.norm * a2.y + e3.norm * a3.y;
        a0 = h2f(v0.z); a1 = h2f(v1.z); a2 = h2f(v2.z); a3 = h2f(v3.z);
        acc[4] += e0.norm * a0.x + e1.norm * a1.x + e2.norm * a2.x + e3.norm * a3.x;
        acc[5] += e0.norm * a0.y + e1.norm * a1.y + e2.norm * a2.y + e3.norm * a3.y;
        a0 = h2f(v0.w); a1 = h2f(v1.w); a2 = h2f(v2.w); a3 = h2f(v3.w);
        acc[6] += e0.norm * a0.x + e1.norm * a1.x + e2.norm * a2.x + e3.norm * a3.x;
        acc[7] += e0.norm * a0.y + e1.norm * a1.y + e2.norm * a2.y + e3.norm * a3.y;
    }
    for (; j < e; j++) {
        EdgeRec e0 = g_edge[j];
        uint4 v0 = *(const uint4*)(h + (size_t)e0.src * D + c);
        float2 a0 = h2f(v0.x), a1 = h2f(v0.y), a2 = h2f(v0.z), a3 = h2f(v0.w);
        acc[0] += e0.norm * a0.x; acc[1] += e0.norm * a0.y;
        acc[2] += e0.norm * a1.x; acc[3] += e0.norm * a1.y;
        acc[4] += e0.norm * a2.x; acc[5] += e0.norm * a2.y;
        acc[6] += e0.norm * a3.x; acc[7] += e0.norm * a3.y;
    }
    __half2 out4[4];
    out4[0] = __floats2half2_rn(acc[0], acc[1]);
    out4[1] = __floats2half2_rn(acc[2], acc[3]);
    out4[2] = __floats2half2_rn(acc[4], acc[5]);
    out4[3] = __floats2half2_rn(acc[6], acc[7]);
    *(uint4*)(g_Ah + (size_t)node * D + c) = *(uint4*)out4;
}
// layer 0: gather g_x16, 16 threads/node, 16 nodes/block
__global__ void __launch_bounds__(256) k_agg_x() {
    int node = blockIdx.x * 16 + (threadIdx.x >> 4);
    if (node >= NODES) return;
    agg_body16<FIN>(g_x16, node, (threadIdx.x & 15) * 8);
}
// layers 1,2: gather g_h, 32 threads/node, 8 nodes/block
__global__ void __launch_bounds__(256) k_agg_h() {
    int node = blockIdx.x * 8 + (threadIdx.x >> 5);
    if (node >= NODES) return;
    agg_body16<FH>(g_h, node, (threadIdx.x & 31) * 8);
}

// ================= HMMA GEMM (fp16 single-pass, 3-stage pipeline) ===========
#define SMEM_TOTAL 98304
__global__ void __launch_bounds__(256, 2) k_mma(int K, int layer) {
    extern __shared__ char smem[];
    uint32_t sb = smem_u32(smem);
    int tid = threadIdx.x, lane = tid & 31, wid = tid >> 5;
    int wm = wid >> 2, wn = wid & 3;
    int m0 = blockIdx.x * 128, bn = blockIdx.y * 128;
    int nch = K >> 6;
    const __half* W = (layer == 0) ? g_W0 : (layer == 1) ? g_W1 : g_W2;

    float acc[4][4][4];
    #pragma unroll
    for (int i = 0; i < 4; i++)
        #pragma unroll
        for (int j = 0; j < 4; j++)
            #pragma unroll
            for (int q = 0; q < 4; q++) acc[i][j][q] = 0.f;

    auto issue = [&](int c) {
        int k0 = c << 6;
        uint32_t ao = (uint32_t)(c % 3) * 32768u;
        uint32_t bo = ao + 16384u;
        #pragma unroll
        for (int i = 0; i < 4; i++) {
            int idx = tid + i * 256;
            int r = idx >> 3, v = idx & 7;
            int gr = m0 + r;
            int ok = gr < NODES;
            const __half* src = g_Ah + (size_t)(ok ? gr : 0) * K + k0 + v * 8;
            uint32_t dst = sb + ao + sw128((uint32_t)(r * 128 + v * 16));
            unsigned long long gs = (unsigned long long)__cvta_generic_to_global((void*)src);
            int sz = ok ? 16 : 0;
            asm volatile("cp.async.cg.shared.global [%0], [%1], 16, %2;" :: "r"(dst), "l"(gs), "r"(sz));
        }
        #pragma unroll
        for (int i = 0; i < 4; i++) {
            int idx = tid + i * 256;
            int r = idx >> 3, v = idx & 7;
            const __half* src = W + (size_t)(bn + r) * K + k0 + v * 8;
            uint32_t dst = sb + bo + sw128((uint32_t)(r * 128 + v * 16));
            unsigned long long gs = (unsigned long long)__cvta_generic_to_global((void*)src);
            asm volatile("cp.async.cg.shared.global [%0], [%1], 16;" :: "r"(dst), "l"(gs));
        }
        asm volatile("cp.async.commit_group;" ::: "memory");
    };

    issue(0);
    if (nch > 1) issue(1);

    int grp = lane >> 3;
    int rr = (lane & 7) + ((grp & 1) << 3);
    int kof = (grp >= 2) ? 16 : 0;

    for (int c = 0; c < nch; c++) {
        if (c + 2 < nch) { issue(c + 2); asm volatile("cp.async.wait_group 2;" ::: "memory"); }
        else if (c + 1 < nch) { asm volatile("cp.async.wait_group 1;" ::: "memory"); }
        else { asm volatile("cp.async.wait_group 0;" ::: "memory"); }
        __syncthreads();
        uint32_t ab = sb + (uint32_t)(c % 3) * 32768u;
        uint32_t bb = ab + 16384u;
        #pragma unroll
        for (int kk = 0; kk < 4; kk++) {
            uint32_t a[4][4], bf[2][4];
            #pragma unroll
            for (int mt = 0; mt < 4; mt++) {
                uint32_t addr = ab + sw128((uint32_t)((wm * 64 + mt * 16 + rr) * 128 + kk * 32 + kof));
                asm volatile("ldmatrix.sync.aligned.m8n8.x4.shared.b16 {%0,%1,%2,%3}, [%4];"
                    : "=r"(a[mt][0]), "=r"(a[mt][1]), "=r"(a[mt][2]), "=r"(a[mt][3]) : "r"(addr));
            }
            #pragma unroll
            for (int p = 0; p < 2; p++) {
                uint32_t addr = bb + sw128((uint32_t)((wn * 32 + p * 16 + rr) * 128 + kk * 32 + kof));
                asm volatile("ldmatrix.sync.aligned.m8n8.x4.shared.b16 {%0,%1,%2,%3}, [%4];"
                    : "=r"(bf[p][0]), "=r"(bf[p][1]), "=r"(bf[p][2]), "=r"(bf[p][3]) : "r"(addr));
            }
            #pragma unroll
            for (int mt = 0; mt < 4; mt++)
                #pragma unroll
                for (int nt = 0; nt < 4; nt++) {
                    uint32_t b0 = bf[nt >> 1][nt & 1];
                    uint32_t b1 = bf[nt >> 1][(nt & 1) + 2];
                    asm volatile("mma.sync.aligned.m16n8k16.row.col.f32.f16.f16.f32 "
                        "{%0,%1,%2,%3}, {%4,%5,%6,%7}, {%8,%9}, {%0,%1,%2,%3};"
                        : "+f"(acc[mt][nt][0]), "+f"(acc[mt][nt][1]),
                          "+f"(acc[mt][nt][2]), "+f"(acc[mt][nt][3])
                        : "r"(a[mt][0]), "r"(a[mt][1]), "r"(a[mt][2]), "r"(a[mt][3]),
                          "r"(b0), "r"(b1));
                }
        }
        __syncthreads();
    }

    // epilogue: relu; layers 0,1 -> fp16 g_h, layer 2 -> fp32 g_bufA
    int colb = bn + wn * 32 + 2 * (lane & 3);
    bool f16out = (layer < 2);
    #pragma unroll
    for (int mt = 0; mt < 4; mt++) {
        int row = m0 + wm * 64 + mt * 16 + (lane >> 2);
        #pragma unroll
        for (int nt = 0; nt < 4; nt++) {
            float v0 = fmaxf(acc[mt][nt][0], 0.f), v1 = fmaxf(acc[mt][nt][1], 0.f);
            float v2 = fmaxf(acc[mt][nt][2], 0.f), v3 = fmaxf(acc[mt][nt][3], 0.f);
            if (f16out) {
                if (row < NODES)
                    *(__half2*)(g_h + (size_t)row * FH + colb + nt * 8) = __floats2half2_rn(v0, v1);
                if (row + 8 < NODES)
                    *(__half2*)(g_h + (size_t)(row + 8) * FH + colb + nt * 8) = __floats2half2_rn(v2, v3);
            } else {
                if (row < NODES)
                    *(float2*)(g_bufA + (size_t)row * FH + colb + nt * 8) = make_float2(v0, v1);
                if (row + 8 < NODES)
                    *(float2*)(g_bufA + (size_t)(row + 8) * FH + colb + nt * 8) = make_float2(v2, v3);
            }
        }
    }
}

// ================= fused pool + MLP head ====================================
__global__ void __launch_bounds__(256) k_poolhead(
        const float* __restrict__ Wm1, const float* __restrict__ bm1,
        const float* __restrict__ Wm2, const float* __restrict__ bm2,
        float* __restrict__ out) {
    __shared__ float4 red[4][64];
    __shared__ float sp[FH];
    __shared__ float sh[FH];
    __shared__ float sl[FOUT];
    __shared__ float s_m, s_lse;
    int g = blockIdx.x;
    int t = threadIdx.x, cg = t & 63, rg = t >> 6;
    int s = g_gstart[g], e = g_gstart[g + 1];
    {
        int c = cg * 4;
        float4 acc = make_float4(0.f, 0.f, 0.f, 0.f);
        for (int i = s + rg; i < e; i += 4) {
            float4 v = *(const float4*)(g_bufA + (size_t)i * FH + c);
            acc.x += v.x; acc.y += v.y; acc.z += v.z; acc.w += v.w;
        }
        red[rg][cg] = acc;
    }
    __syncthreads();
    if (rg == 0) {
        float4 a0 = red[0][cg], a1 = red[1][cg], a2 = red[2][cg], a3 = red[3][cg];
        int cnt = e - s;
        float inv = 1.0f / (float)(cnt > 0 ? cnt : 1);
        int c = cg * 4;
        sp[c]     = (a0.x + a1.x + a2.x + a3.x) * inv;
        sp[c + 1] = (a0.y + a1.y + a2.y + a3.y) * inv;
        sp[c + 2] = (a0.z + a1.z + a2.z + a3.z) * inv;
        sp[c + 3] = (a0.w + a1.w + a2.w + a3.w) * inv;
    }
    __syncthreads();
    float acc = bm1[t];
    #pragma unroll 8
    for (int k = 0; k < FH; k++) acc += sp[k] * Wm1[k * FH + t];
    sh[t] = acc > 0.f ? acc : 0.f;
    __syncthreads();
    if (t < FOUT) {
        float a = bm2[t];
        for (int k = 0; k < FH; k++) a += sh[k] * Wm2[k * FOUT + t];
        sl[t] = a;
    }
    __syncthreads();
    if (t == 0) {
        float m = sl[0];
        for (int o = 1; o < FOUT; o++) m = fmaxf(m, sl[o]);
        float sum = 0.f;
        for (int o = 0; o < FOUT; o++) sum += expf(sl[o] - m);
        s_m = m; s_lse = logf(sum);
    }
    __syncthreads();
    if (t < FOUT) {
        float v = sl[t];
        out[g * FOUT + t]                     = v - s_m - s_lse;
        out[NGRAPH * FOUT + g * FOUT + t]     = 1.0f / (1.0f + expf(-v));
        out[2 * NGRAPH * FOUT + g * FOUT + t] = v;
    }
}

// ================= launch ===================================================
extern "C" void kernel_launch(void* const* d_in, const int* in_sizes, int n_in,
                              void* d_out, int out_size) {
    const float* x     = (const float*)d_in[0];
    const void*  ei    = d_in[1];
    const void*  batch = d_in[3];
    const float* W0  = (const float*)d_in[4];
    const float* W1  = (const float*)d_in[5];
    const float* W2  = (const float*)d_in[6];
    const float* Wm1 = (const float*)d_in[7];
    const float* bm1 = (const float*)d_in[8];
    const float* Wm2 = (const float*)d_in[9];
    const float* bm2 = (const float*)d_in[10];
    float* out = (float*)d_out;

    cudaFuncSetAttribute(k_mma, cudaFuncAttributeMaxDynamicSharedMemorySize, SMEM_TOTAL);

    // ---- graph structure + conversions
    k_zero<<<(NODES + 255) / 256, 256>>>((const int*)ei);
    k_hist<<<(EDGES + 255) / 256, 256>>>(ei, batch);
    k_scan1<<<SCAN_BLOCKS, 1024>>>();
    k_scan2<<<1, NGRAPH>>>();
    k_scatter<<<(EDGES + 255) / 256, 256>>>(ei);
    k_conv<<<(NODES * FIN / 4 + 255) / 256, 256>>>(x, W0, W1, W2);

    dim3 mg((NODES + 127) / 128, 2);

    // ---- layer 0
    k_agg_x<<<(NODES + 15) / 16, 256>>>();
    k_mma<<<mg, 256, SMEM_TOTAL>>>(FIN, 0);
    // ---- layer 1
    k_agg_h<<<(NODES + 7) / 8, 256>>>();
    k_mma<<<mg, 256, SMEM_TOTAL>>>(FH, 1);
    // ---- layer 2
    k_agg_h<<<(NODES + 7) / 8, 256>>>();
    k_mma<<<mg, 256, SMEM_TOTAL>>>(FH, 2);

    // ---- fused pool + head
    k_poolhead<<<NGRAPH, 256>>>(Wm1, bm1, Wm2, bm2, out);
}

// round 14
// speedup vs baseline: 3.8230x; 1.0335x over previous
#include <cuda_runtime.h>
#include <cuda_fp16.h>
#include <math.h>
#include <stdint.h>

#define NODES 50000
#define EDGES 800000
#define FIN   128
#define FH    256
#define FOUT  10
#define NGRAPH 128
#define SCAN_BLOCKS 49   // ceil(50000/1024)

__device__ __forceinline__ uint32_t smem_u32(const void* p) {
    uint32_t a;
    asm("{ .reg .u64 t; cvta.to.shared.u64 t, %1; cvt.u32.u64 %0, t; }" : "=r"(a) : "l"(p));
    return a;
}
__device__ __forceinline__ uint32_t sw128(uint32_t off) { return off ^ ((off >> 3) & 0x70); }
__device__ __forceinline__ float2 h2f(uint32_t u) {
    __half2 h = *reinterpret_cast<__half2*>(&u);
    return __half22float2(h);
}

// ================= scratch ==================================================
__device__ __half  g_h[(size_t)NODES * FH];      // layer outputs (prescaled h' for L0/L1; plain relu for L2)
__device__ __half  g_x16[(size_t)NODES * FIN];   // dinv-scaled x in fp16
__device__ __half  g_Ah[(size_t)NODES * FH];     // agg output (GEMM A input)
__device__ __half  g_W0[FH * FIN];               // weights [N=256][K] fp16
__device__ __half  g_W1[FH * FH];
__device__ __half  g_W2[FH * FH];
__device__ float   g_dinv[NODES];
__device__ int     g_deg[NODES];
__device__ int     g_rowptr[NODES + 1];          // block-local prefix (+ g_boff)
__device__ int     g_cursor[NODES];
__device__ int     g_bsum[SCAN_BLOCKS];
__device__ int     g_boff[SCAN_BLOCKS];
__device__ int     g_ticket;
__device__ int     g_src[EDGES];                 // CSR source ids (4B/edge)
__device__ int     g_gcount[NGRAPH];
__device__ int     g_gstart[NGRAPH + 1];
__device__ int     g_is64;

__device__ __forceinline__ int load_idx(const void* p, size_t i) {
    return g_is64 ? (int)((const long long*)p)[i] : ((const int*)p)[i];
}

// ================= zero + dtype probe (fused) ===============================
__global__ void k_zero(const int* __restrict__ ei32) {
    int i = blockIdx.x * blockDim.x + threadIdx.x;
    if (blockIdx.x == 0) {
        __shared__ int nonzero;
        if (threadIdx.x == 0) nonzero = 0;
        __syncthreads();
        int stride = (2 * EDGES) / 256;
        int pos = threadIdx.x * stride + 1;
        if (ei32[pos | 1] != 0) atomicOr(&nonzero, 1);
        __syncthreads();
        if (threadIdx.x == 0) { g_is64 = nonzero ? 0 : 1; g_ticket = 0; }
    }
    if (i < NODES) { g_deg[i] = 0; g_cursor[i] = 0; }
    if (i < NGRAPH) g_gcount[i] = 0;
}

// ================= histograms ===============================================
__global__ void k_hist(const void* __restrict__ ei, const void* __restrict__ batch) {
    int i = blockIdx.x * blockDim.x + threadIdx.x;
    if (i < EDGES) atomicAdd(&g_deg[load_idx(ei, (size_t)EDGES + i)], 1);
    if (i < NODES) atomicAdd(&g_gcount[load_idx(batch, i)], 1);
}

// ================= single-kernel scan (last block finishes, race-free) ======
__global__ void __launch_bounds__(1024) k_scan1() {
    __shared__ int wsum[32];
    __shared__ int is_last;
    __shared__ int gs[NGRAPH];
    int t = threadIdx.x, lane = t & 31, w = t >> 5;
    int i = blockIdx.x * 1024 + t;
    int v = 0;
    if (i < NODES) {
        v = g_deg[i];
        g_dinv[i] = rsqrtf((float)v + 1.0f);
    }
    int x = v;
    #pragma unroll
    for (int off = 1; off < 32; off <<= 1) {
        int y = __shfl_up_sync(0xFFFFFFFFu, x, off);
        if (lane >= off) x += y;
    }
    if (lane == 31) wsum[w] = x;
    __syncthreads();
    if (w == 0) {
        int s = wsum[lane];
        #pragma unroll
        for (int off = 1; off < 32; off <<= 1) {
            int y = __shfl_up_sync(0xFFFFFFFFu, s, off);
            if (lane >= off) s += y;
        }
        wsum[lane] = s;
    }
    __syncthreads();
    int woff = (w > 0) ? wsum[w - 1] : 0;
    if (i <= NODES) g_rowptr[i] = woff + x - v;
    if (t == 1023) {
        g_bsum[blockIdx.x] = wsum[31];
        __threadfence();                       // writer's fence BEFORE ticket
    }
    __syncthreads();                            // bsum write ordered before ticket
    if (t == 0) {
        int prev = atomicAdd(&g_ticket, 1);
        is_last = (prev == SCAN_BLOCKS - 1);
        if (is_last) __threadfence();           // acquire side
    }
    __syncthreads();
    if (!is_last) return;                       // uniform per block: all threads agree
    // ---- last block: finish block-sum scan + graph-count scan (all threads in barriers)
    if (t == 0) {
        int run = 0;
        for (int b = 0; b < SCAN_BLOCKS; b++) { g_boff[b] = run; run += g_bsum[b]; }
    }
    if (t < NGRAPH) gs[t] = g_gcount[t];
    __syncthreads();
    for (int off = 1; off < NGRAPH; off <<= 1) {
        int add = (t >= off && t < NGRAPH) ? gs[t - off] : 0;
        __syncthreads();
        if (t < NGRAPH) gs[t] += add;
        __syncthreads();
    }
    if (t < NGRAPH) {
        g_gstart[t] = gs[t] - g_gcount[t];      // exclusive
        if (t == NGRAPH - 1) g_gstart[NGRAPH] = gs[t];
    }
}
__device__ __forceinline__ int rowptr_abs(int i) {
    return g_rowptr[i] + g_boff[i >> 10];
}

__global__ void k_scatter(const void* __restrict__ ei) {
    int e = blockIdx.x * blockDim.x + threadIdx.x;
    if (e >= EDGES) return;
    int row = load_idx(ei, e);
    int col = load_idx(ei, (size_t)EDGES + e);
    int pos = atomicAdd(&g_cursor[col], 1);
    g_src[rowptr_abs(col) + pos] = row;
}

// ================= weights + dinv-scaled x conversion =======================
#define NWELEM (256 * FIN + 2 * 256 * FH)   // 163840
__global__ void k_conv(const float* __restrict__ x, const float* __restrict__ W0,
                       const float* __restrict__ W1, const float* __restrict__ W2) {
    int i = blockIdx.x * blockDim.x + threadIdx.x;
    if (i < NODES * FIN / 4) {
        float4 v = ((const float4*)x)[i];
        float di = g_dinv[(i * 4) >> 7];       // 128 cols per row
        __half2* dst = (__half2*)(g_x16 + (size_t)i * 4);
        dst[0] = __floats2half2_rn(di * v.x, di * v.y);
        dst[1] = __floats2half2_rn(di * v.z, di * v.w);
    }
    if (i < NWELEM) {
        float w; __half* dst;
        if (i < 256 * FIN) {
            int n = i / FIN, k = i - n * FIN;
            w = W0[(size_t)k * FH + n]; dst = g_W0 + i;
        } else if (i < 256 * FIN + 256 * FH) {
            int j = i - 256 * FIN;
            int n = j / FH, k = j - n * FH;
            w = W1[(size_t)k * FH + n]; dst = g_W1 + j;
        } else {
            int j = i - 256 * FIN - 256 * FH;
            int n = j / FH, k = j - n * FH;
            w = W2[(size_t)k * FH + n]; dst = g_W2 + j;
        }
        *dst = __float2half(w);
    }
}

// ================= aggregation (fp16 gather of prescaled h', pure sums) =====
// agg_i = dinv_i * (h'_i + sum_{j in N(i)} h'_j)
template <int D>
__device__ __forceinline__ void agg_body16(const __half* __restrict__ h, int node, int c) {
    int s = rowptr_abs(node), e = rowptr_abs(node + 1);
    float di = g_dinv[node];
    uint4 sv = *(const uint4*)(h + (size_t)node * D + c);
    float2 p0 = h2f(sv.x), p1 = h2f(sv.y), p2 = h2f(sv.z), p3 = h2f(sv.w);
    float acc[8] = { p0.x, p0.y, p1.x, p1.y, p2.x, p2.y, p3.x, p3.y };
    int j = s;
    for (; j + 3 < e; j += 4) {
        int s0 = g_src[j], s1 = g_src[j + 1], s2 = g_src[j + 2], s3 = g_src[j + 3];
        uint4 v0 = *(const uint4*)(h + (size_t)s0 * D + c);
        uint4 v1 = *(const uint4*)(h + (size_t)s1 * D + c);
        uint4 v2 = *(const uint4*)(h + (size_t)s2 * D + c);
        uint4 v3 = *(const uint4*)(h + (size_t)s3 * D + c);
        float2 a0, a1, a2, a3;
        a0 = h2f(v0.x); a1 = h2f(v1.x); a2 = h2f(v2.x); a3 = h2f(v3.x);
        acc[0] += (a0.x + a1.x) + (a2.x + a3.x);
        acc[1] += (a0.y + a1.y) + (a2.y + a3.y);
        a0 = h2f(v0.y); a1 = h2f(v1.y); a2 = h2f(v2.y); a3 = h2f(v3.y);
        acc[2] += (a0.x + a1.x) + (a2.x + a3.x);
        acc[3] += (a0.y + a1.y) + (a2.y + a3.y);
        a0 = h2f(v0.z); a1 = h2f(v1.z); a2 = h2f(v2.z); a3 = h2f(v3.z);
        acc[4] += (a0.x + a1.x) + (a2.x + a3.x);
        acc[5] += (a0.y + a1.y) + (a2.y + a3.y);
        a0 = h2f(v0.w); a1 = h2f(v1.w); a2 = h2f(v2.w); a3 = h2f(v3.w);
        acc[6] += (a0.x + a1.x) + (a2.x + a3.x);
        acc[7] += (a0.y + a1.y) + (a2.y + a3.y);
    }
    for (; j < e; j++) {
        uint4 v0 = *(const uint4*)(h + (size_t)g_src[j] * D + c);
        float2 a0 = h2f(v0.x), a1 = h2f(v0.y), a2 = h2f(v0.z), a3 = h2f(v0.w);
        acc[0] += a0.x; acc[1] += a0.y;
        acc[2] += a1.x; acc[3] += a1.y;
        acc[4] += a2.x; acc[5] += a2.y;
        acc[6] += a3.x; acc[7] += a3.y;
    }
    __half2 out4[4];
    out4[0] = __floats2half2_rn(di * acc[0], di * acc[1]);
    out4[1] = __floats2half2_rn(di * acc[2], di * acc[3]);
    out4[2] = __floats2half2_rn(di * acc[4], di * acc[5]);
    out4[3] = __floats2half2_rn(di * acc[6], di * acc[7]);
    *(uint4*)(g_Ah + (size_t)node * D + c) = *(uint4*)out4;
}
__global__ void __launch_bounds__(256) k_agg_x() {
    int node = blockIdx.x * 16 + (threadIdx.x >> 4);
    if (node >= NODES) return;
    agg_body16<FIN>(g_x16, node, (threadIdx.x & 15) * 8);
}
__global__ void __launch_bounds__(256) k_agg_h() {
    int node = blockIdx.x * 8 + (threadIdx.x >> 5);
    if (node >= NODES) return;
    agg_body16<FH>(g_h, node, (threadIdx.x & 31) * 8);
}

// ================= HMMA GEMM (fp16 single-pass, 3-stage pipeline) ===========
// layers 0,1: g_h = dinv * relu(Ah @ W^T)   (prescaled for next agg)
// layer  2:   g_h = relu(Ah @ W^T)          (plain, for pooling)
#define SMEM_TOTAL 98304
__global__ void __launch_bounds__(256, 2) k_mma(int K, int layer) {
    extern __shared__ char smem[];
    uint32_t sb = smem_u32(smem);
    int tid = threadIdx.x, lane = tid & 31, wid = tid >> 5;
    int wm = wid >> 2, wn = wid & 3;
    int m0 = blockIdx.x * 128, bn = blockIdx.y * 128;
    int nch = K >> 6;
    const __half* W = (layer == 0) ? g_W0 : (layer == 1) ? g_W1 : g_W2;

    float acc[4][4][4];
    #pragma unroll
    for (int i = 0; i < 4; i++)
        #pragma unroll
        for (int j = 0; j < 4; j++)
            #pragma unroll
            for (int q = 0; q < 4; q++) acc[i][j][q] = 0.f;

    auto issue = [&](int c) {
        int k0 = c << 6;
        uint32_t ao = (uint32_t)(c % 3) * 32768u;
        uint32_t bo = ao + 16384u;
        #pragma unroll
        for (int i = 0; i < 4; i++) {
            int idx = tid + i * 256;
            int r = idx >> 3, v = idx & 7;
            int gr = m0 + r;
            int ok = gr < NODES;
            const __half* src = g_Ah + (size_t)(ok ? gr : 0) * K + k0 + v * 8;
            uint32_t dst = sb + ao + sw128((uint32_t)(r * 128 + v * 16));
            unsigned long long gs = (unsigned long long)__cvta_generic_to_global((void*)src);
            int sz = ok ? 16 : 0;
            asm volatile("cp.async.cg.shared.global [%0], [%1], 16, %2;" :: "r"(dst), "l"(gs), "r"(sz));
        }
        #pragma unroll
        for (int i = 0; i < 4; i++) {
            int idx = tid + i * 256;
            int r = idx >> 3, v = idx & 7;
            const __half* src = W + (size_t)(bn + r) * K + k0 + v * 8;
            uint32_t dst = sb + bo + sw128((uint32_t)(r * 128 + v * 16));
            unsigned long long gs = (unsigned long long)__cvta_generic_to_global((void*)src);
            asm volatile("cp.async.cg.shared.global [%0], [%1], 16;" :: "r"(dst), "l"(gs));
        }
        asm volatile("cp.async.commit_group;" ::: "memory");
    };

    issue(0);
    if (nch > 1) issue(1);

    int grp = lane >> 3;
    int rr = (lane & 7) + ((grp & 1) << 3);
    int kof = (grp >= 2) ? 16 : 0;

    for (int c = 0; c < nch; c++) {
        if (c + 2 < nch) { issue(c + 2); asm volatile("cp.async.wait_group 2;" ::: "memory"); }
        else if (c + 1 < nch) { asm volatile("cp.async.wait_group 1;" ::: "memory"); }
        else { asm volatile("cp.async.wait_group 0;" ::: "memory"); }
        __syncthreads();
        uint32_t ab = sb + (uint32_t)(c % 3) * 32768u;
        uint32_t bb = ab + 16384u;
        #pragma unroll
        for (int kk = 0; kk < 4; kk++) {
            uint32_t a[4][4], bf[2][4];
            #pragma unroll
            for (int mt = 0; mt < 4; mt++) {
                uint32_t addr = ab + sw128((uint32_t)((wm * 64 + mt * 16 + rr) * 128 + kk * 32 + kof));
                asm volatile("ldmatrix.sync.aligned.m8n8.x4.shared.b16 {%0,%1,%2,%3}, [%4];"
                    : "=r"(a[mt][0]), "=r"(a[mt][1]), "=r"(a[mt][2]), "=r"(a[mt][3]) : "r"(addr));
            }
            #pragma unroll
            for (int p = 0; p < 2; p++) {
                uint32_t addr = bb + sw128((uint32_t)((wn * 32 + p * 16 + rr) * 128 + kk * 32 + kof));
                asm volatile("ldmatrix.sync.aligned.m8n8.x4.shared.b16 {%0,%1,%2,%3}, [%4];"
                    : "=r"(bf[p][0]), "=r"(bf[p][1]), "=r"(bf[p][2]), "=r"(bf[p][3]) : "r"(addr));
            }
            #pragma unroll
            for (int mt = 0; mt < 4; mt++)
                #pragma unroll
                for (int nt = 0; nt < 4; nt++) {
                    uint32_t b0 = bf[nt >> 1][nt & 1];
                    uint32_t b1 = bf[nt >> 1][(nt & 1) + 2];
                    asm volatile("mma.sync.aligned.m16n8k16.row.col.f32.f16.f16.f32 "
                        "{%0,%1,%2,%3}, {%4,%5,%6,%7}, {%8,%9}, {%0,%1,%2,%3};"
                        : "+f"(acc[mt][nt][0]), "+f"(acc[mt][nt][1]),
                          "+f"(acc[mt][nt][2]), "+f"(acc[mt][nt][3])
                        : "r"(a[mt][0]), "r"(a[mt][1]), "r"(a[mt][2]), "r"(a[mt][3]),
                          "r"(b0), "r"(b1));
                }
        }
        __syncthreads();
    }

    // epilogue: relu (+dinv prescale for layers 0,1), fp16 store to g_h
    int colb = bn + wn * 32 + 2 * (lane & 3);
    bool prescale = (layer < 2);
    #pragma unroll
    for (int mt = 0; mt < 4; mt++) {
        int row = m0 + wm * 64 + mt * 16 + (lane >> 2);
        float d0 = 1.f, d1 = 1.f;
        if (prescale) {
            if (row < NODES) d0 = g_dinv[row];
            if (row + 8 < NODES) d1 = g_dinv[row + 8];
        }
        #pragma unroll
        for (int nt = 0; nt < 4; nt++) {
            float v0 = d0 * fmaxf(acc[mt][nt][0], 0.f), v1 = d0 * fmaxf(acc[mt][nt][1], 0.f);
            float v2 = d1 * fmaxf(acc[mt][nt][2], 0.f), v3 = d1 * fmaxf(acc[mt][nt][3], 0.f);
            if (row < NODES)
                *(__half2*)(g_h + (size_t)row * FH + colb + nt * 8) = __floats2half2_rn(v0, v1);
            if (row + 8 < NODES)
                *(__half2*)(g_h + (size_t)(row + 8) * FH + colb + nt * 8) = __floats2half2_rn(v2, v3);
        }
    }
}

// ================= fused pool + MLP head (fp16 input) =======================
__global__ void __launch_bounds__(256) k_poolhead(
        const float* __restrict__ Wm1, const float* __restrict__ bm1,
        const float* __restrict__ Wm2, const float* __restrict__ bm2,
        float* __restrict__ out) {
    __shared__ float4 red[4][64];
    __shared__ float sp[FH];
    __shared__ float sh[FH];
    __shared__ float sl[FOUT];
    __shared__ float s_m, s_lse;
    int g = blockIdx.x;
    int t = threadIdx.x, cg = t & 63, rg = t >> 6;
    int s = g_gstart[g], e = g_gstart[g + 1];
    {
        int c = cg * 4;
        float4 acc = make_float4(0.f, 0.f, 0.f, 0.f);
        for (int i = s + rg; i < e; i += 4) {
            uint2 u = *(const uint2*)(g_h + (size_t)i * FH + c);
            float2 a0 = h2f(u.x), a1 = h2f(u.y);
            acc.x += a0.x; acc.y += a0.y; acc.z += a1.x; acc.w += a1.y;
        }
        red[rg][cg] = acc;
    }
    __syncthreads();
    if (rg == 0) {
        float4 a0 = red[0][cg], a1 = red[1][cg], a2 = red[2][cg], a3 = red[3][cg];
        int cnt = e - s;
        float inv = 1.0f / (float)(cnt > 0 ? cnt : 1);
        int c = cg * 4;
        sp[c]     = (a0.x + a1.x + a2.x + a3.x) * inv;
        sp[c + 1] = (a0.y + a1.y + a2.y + a3.y) * inv;
        sp[c + 2] = (a0.z + a1.z + a2.z + a3.z) * inv;
        sp[c + 3] = (a0.w + a1.w + a2.w + a3.w) * inv;
    }
    __syncthreads();
    float acc = bm1[t];
    #pragma unroll 8
    for (int k = 0; k < FH; k++) acc += sp[k] * Wm1[k * FH + t];
    sh[t] = acc > 0.f ? acc : 0.f;
    __syncthreads();
    if (t < FOUT) {
        float a = bm2[t];
        for (int k = 0; k < FH; k++) a += sh[k] * Wm2[k * FOUT + t];
        sl[t] = a;
    }
    __syncthreads();
    if (t == 0) {
        float m = sl[0];
        for (int o = 1; o < FOUT; o++) m = fmaxf(m, sl[o]);
        float sum = 0.f;
        for (int o = 0; o < FOUT; o++) sum += expf(sl[o] - m);
        s_m = m; s_lse = logf(sum);
    }
    __syncthreads();
    if (t < FOUT) {
        float v = sl[t];
        out[g * FOUT + t]                     = v - s_m - s_lse;
        out[NGRAPH * FOUT + g * FOUT + t]     = 1.0f / (1.0f + expf(-v));
        out[2 * NGRAPH * FOUT + g * FOUT + t] = v;
    }
}

// ================= launch ===================================================
extern "C" void kernel_launch(void* const* d_in, const int* in_sizes, int n_in,
                              void* d_out, int out_size) {
    const float* x     = (const float*)d_in[0];
    const void*  ei    = d_in[1];
    const void*  batch = d_in[3];
    const float* W0  = (const float*)d_in[4];
    const float* W1  = (const float*)d_in[5];
    const float* W2  = (const float*)d_in[6];
    const float* Wm1 = (const float*)d_in[7];
    const float* bm1 = (const float*)d_in[8];
    const float* Wm2 = (const float*)d_in[9];
    const float* bm2 = (const float*)d_in[10];
    float* out = (float*)d_out;

    cudaFuncSetAttribute(k_mma, cudaFuncAttributeMaxDynamicSharedMemorySize, SMEM_TOTAL);

    // ---- graph structure + conversions
    k_zero<<<(NODES + 255) / 256, 256>>>((const int*)ei);
    k_hist<<<(EDGES + 255) / 256, 256>>>(ei, batch);
    k_scan1<<<SCAN_BLOCKS, 1024>>>();
    k_conv<<<(NODES * FIN / 4 + 255) / 256, 256>>>(x, W0, W1, W2);
    k_scatter<<<(EDGES + 255) / 256, 256>>>(ei);

    dim3 mg((NODES + 127) / 128, 2);

    // ---- layer 0
    k_agg_x<<<(NODES + 15) / 16, 256>>>();
    k_mma<<<mg, 256, SMEM_TOTAL>>>(FIN, 0);
    // ---- layer 1
    k_agg_h<<<(NODES + 7) / 8, 256>>>();
    k_mma<<<mg, 256, SMEM_TOTAL>>>(FH, 1);
    // ---- layer 2
    k_agg_h<<<(NODES + 7) / 8, 256>>>();
    k_mma<<<mg, 256, SMEM_TOTAL>>>(FH, 2);

    // ---- fused pool + head
    k_poolhead<<<NGRAPH, 256>>>(Wm1, bm1, Wm2, bm2, out);
}